// round 11
// baseline (speedup 1.0000x reference)
#include <cuda_runtime.h>
#include <cstdint>

#define BATCH 8
#define HH    64
#define WW_   64
#define TT    4096
#define CC    256
#define DD    512
#define MM    (BATCH * TT)   // 32768

#define NCHAIN 4096
#define NCHUNK 32
#define CHLEN  128

// ---------------- scratch (static device globals; no runtime alloc) ----------
__device__ float g_comb[25 * CC];
__device__ float g_xf[BATCH * TT * CC];     // tf32-rounded activations
__device__ float g_k [BATCH * TT * CC];
__device__ float g_v [BATCH * TT * CC];
__device__ float g_sr[BATCH * TT * CC];
__device__ float g_xs[BATCH * TT * DD];     // tf32-rounded scan output
__device__ float g_sa[NCHUNK * NCHAIN];
__device__ float g_sb[NCHUNK * NCHAIN];
__device__ float g_sp[NCHUNK * NCHAIN];
__device__ float g_pa[NCHUNK * NCHAIN];
__device__ float g_pb[NCHUNK * NCHAIN];
__device__ float g_pp[NCHUNK * NCHAIN];
// tf32-rounded weights
__device__ float g_wk[CC * CC];
__device__ float g_wv[CC * CC];
__device__ float g_wr[CC * CC];
__device__ float g_wo[CC * DD];

__device__ __forceinline__ unsigned f2tf32(float f) {
    unsigned u;
    asm("cvt.rna.tf32.f32 %0, %1;" : "=r"(u) : "f"(f));
    return u;
}
__device__ __forceinline__ float rnd_tf32(float f) {
    return __uint_as_float(f2tf32(f));
}
__device__ __forceinline__ uint32_t smem_u32(const void* p) {
    uint32_t a;
    asm("{ .reg .u64 t; cvta.to.shared.u64 t, %1; cvt.u32.u64 %0, t; }"
        : "=r"(a) : "l"(p));
    return a;
}
__device__ __forceinline__ void cp16(uint32_t dst, const void* src) {
    asm volatile("cp.async.ca.shared.global [%0], [%1], 16;" :: "r"(dst), "l"(src));
}
#define CP_COMMIT() asm volatile("cp.async.commit_group;" ::: "memory")
#define CP_WAIT1()  asm volatile("cp.async.wait_group 1;"  ::: "memory")

// ---------------- 0) round weights to tf32 grid ------------------------------
__global__ void round_weights_kernel(const float* __restrict__ Wk,
                                     const float* __restrict__ Wv,
                                     const float* __restrict__ Wr,
                                     const float* __restrict__ Wo)
{
    int i = blockIdx.x * 256 + threadIdx.x;
    if (i < CC * CC) {
        g_wk[i] = rnd_tf32(Wk[i]);
        g_wv[i] = rnd_tf32(Wv[i]);
        g_wr[i] = rnd_tf32(Wr[i]);
    }
    if (i < CC * DD) g_wo[i] = rnd_tf32(Wo[i]);
}

// ---------------- 1) combine identity + 1x1 + 3x3 + 5x5 into one 5x5 ---------
__global__ void combine_weights_kernel(const float* __restrict__ alpha,
                                       const float* __restrict__ cw1,
                                       const float* __restrict__ cw3,
                                       const float* __restrict__ cw5)
{
    int c = threadIdx.x;
    float a0 = alpha[0], a1 = alpha[1], a2 = alpha[2], a3 = alpha[3];
    #pragma unroll
    for (int j = 0; j < 5; j++) {
        #pragma unroll
        for (int i = 0; i < 5; i++) {
            float v = a3 * cw5[c * 25 + j * 5 + i];
            if (j >= 1 && j <= 3 && i >= 1 && i <= 3)
                v += a2 * cw3[c * 9 + (j - 1) * 3 + (i - 1)];
            if (j == 2 && i == 2)
                v += a1 * cw1[c] + a0;
            g_comb[(j * 5 + i) * CC + c] = v;
        }
    }
}

// ---------------- 2) depthwise 5x5 conv; output tf32-rounded -----------------
__global__ __launch_bounds__(256) void omni_conv_kernel(const float* __restrict__ x)
{
    int b  = blockIdx.x >> 6;
    int xc = blockIdx.x & 63;
    int c  = threadIdx.x;

    float wgt[25];
    #pragma unroll
    for (int j = 0; j < 25; j++) wgt[j] = g_comb[j * CC + c];

    const float* xin  = x    + (size_t)b * TT * CC + c;
    float*       xout = g_xf + (size_t)b * TT * CC + (size_t)xc * CC + c;

    float win[5][5];
    #pragma unroll
    for (int i = 0; i < 5; i++) { win[0][i] = 0.f; win[1][i] = 0.f; }
    #pragma unroll
    for (int r = 0; r < 3; r++) {
        #pragma unroll
        for (int i = 0; i < 5; i++) {
            int xx = xc - 2 + i;
            win[2 + r][i] = (xx >= 0 && xx < WW_) ? xin[((size_t)r * WW_ + xx) * CC] : 0.f;
        }
    }

    #pragma unroll 2
    for (int y = 0; y < HH; y++) {
        float acc = 0.f;
        #pragma unroll
        for (int j = 0; j < 5; j++)
            #pragma unroll
            for (int i = 0; i < 5; i++)
                acc = fmaf(wgt[j * 5 + i], win[j][i], acc);
        xout[(size_t)y * WW_ * CC] = rnd_tf32(acc);

        #pragma unroll
        for (int j = 0; j < 4; j++)
            #pragma unroll
            for (int i = 0; i < 5; i++) win[j][i] = win[j + 1][i];
        int row = y + 3;
        #pragma unroll
        for (int i = 0; i < 5; i++) {
            int xx = xc - 2 + i;
            win[4][i] = (row < HH && xx >= 0 && xx < WW_)
                        ? xin[((size_t)row * WW_ + xx) * CC] : 0.f;
        }
    }
}

// ---------------- 3) tf32 mma.sync GEMM, 64x64 warp tiles --------------------
// Inputs pre-rounded to tf32 grid -> HW truncation in mma == rna (bit-identical).
// Block 128x128x32 with 4 warps (2x2), warp tile 64x64 (mf=4, nf=8):
// 32 scalar LDS per 32 MMA per k8 (ratio 1.0 vs 1.5 before).
// cp.async 3-stage pipeline; smem rows stride 36 words (conflict-free frags).
#define TILE_W   (128 * 36)                 // words per matrix per stage
#define GS_BYTES (6 * TILE_W * 4)           // 3 stages x (A+B) = 110592 bytes

__global__ __launch_bounds__(128, 2) void gemm_qkv_kernel(
    const float* __restrict__ A,
    const float* __restrict__ W0, const float* __restrict__ W1,
    const float* __restrict__ W2,
    float* __restrict__ O0, float* __restrict__ O1, float* __restrict__ O2,
    int K, int actsel)
{
    extern __shared__ unsigned gsm[];
    const uint32_t smb = smem_u32(gsm);
    const int tid = threadIdx.x;
    const int grp = blockIdx.x >> 1;
    const int bn  = (blockIdx.x & 1) * 128;
    const float* W   = (grp == 0) ? W0 : (grp == 1) ? W1 : W2;
    float*       Out = (grp == 0) ? O0 : (grp == 1) ? O1 : O2;
    const int act = (actsel >> grp) & 1;
    const size_t bm = (size_t)blockIdx.y * 128;

    const int lane = tid & 31, wid = tid >> 5;
    const int wm = (wid & 1) * 64;
    const int wn = (wid >> 1) * 64;
    const int qr = lane >> 2;
    const int qc = lane & 3;

    // cp.async staging: each thread owns one row (0..127) of both tiles
    const float* Ag = A + (bm + tid) * (size_t)K;
    const float* Wg = W + (size_t)(bn + tid) * K;
    const uint32_t dA = smb + (uint32_t)(tid * 36) * 4;

    const int NT = K >> 5;

    float acc[4][8][4];
    #pragma unroll
    for (int mf = 0; mf < 4; mf++)
        #pragma unroll
        for (int nf = 0; nf < 8; nf++)
            #pragma unroll
            for (int i = 0; i < 4; i++) acc[mf][nf][i] = 0.f;

    // prologue: stages 0 and 1 in flight
    #pragma unroll
    for (int s = 0; s < 2; s++) {
        uint32_t da = dA + (uint32_t)(s * 2 * TILE_W) * 4;
        uint32_t db = da + (uint32_t)TILE_W * 4;
        const float* a = Ag + s * 32;
        const float* w = Wg + s * 32;
        #pragma unroll
        for (int j = 0; j < 8; j++) {
            cp16(da + j * 16, a + j * 4);
            cp16(db + j * 16, w + j * 4);
        }
        CP_COMMIT();
    }

    for (int kt = 0; kt < NT; kt++) {
        CP_WAIT1();
        __syncthreads();

        if (kt + 2 < NT) {
            int st = (kt + 2) % 3;
            uint32_t da = dA + (uint32_t)(st * 2 * TILE_W) * 4;
            uint32_t db = da + (uint32_t)TILE_W * 4;
            const float* a = Ag + (kt + 2) * 32;
            const float* w = Wg + (kt + 2) * 32;
            #pragma unroll
            for (int j = 0; j < 8; j++) {
                cp16(da + j * 16, a + j * 4);
                cp16(db + j * 16, w + j * 4);
            }
        }
        CP_COMMIT();

        const unsigned (*As)[36] = (const unsigned (*)[36])(gsm + (kt % 3) * 2 * TILE_W);
        const unsigned (*Ws)[36] = (const unsigned (*)[36])(gsm + (kt % 3) * 2 * TILE_W + TILE_W);

        #pragma unroll
        for (int k8 = 0; k8 < 4; k8++) {
            const int kc = k8 * 8;
            unsigned b0[8], b1[8];
            #pragma unroll
            for (int nf = 0; nf < 8; nf++) {
                int n = wn + nf * 8 + qr;
                b0[nf] = Ws[n][kc + qc];
                b1[nf] = Ws[n][kc + qc + 4];
            }
            #pragma unroll
            for (int mf = 0; mf < 4; mf++) {
                int r0 = wm + mf * 16 + qr;
                unsigned a0 = As[r0][kc + qc];
                unsigned a1 = As[r0 + 8][kc + qc];
                unsigned a2 = As[r0][kc + qc + 4];
                unsigned a3 = As[r0 + 8][kc + qc + 4];
                #pragma unroll
                for (int nf = 0; nf < 8; nf++) {
                    asm volatile(
                        "mma.sync.aligned.m16n8k8.row.col.f32.tf32.tf32.f32 "
                        "{%0,%1,%2,%3}, {%4,%5,%6,%7}, {%8,%9}, {%0,%1,%2,%3};"
                        : "+f"(acc[mf][nf][0]), "+f"(acc[mf][nf][1]),
                          "+f"(acc[mf][nf][2]), "+f"(acc[mf][nf][3])
                        : "r"(a0), "r"(a1), "r"(a2), "r"(a3),
                          "r"(b0[nf]), "r"(b1[nf]));
                }
            }
        }
        __syncthreads();
    }

    #pragma unroll
    for (int mf = 0; mf < 4; mf++) {
        size_t r0 = bm + wm + mf * 16 + qr;
        #pragma unroll
        for (int nf = 0; nf < 8; nf++) {
            int col = bn + wn + nf * 8 + qc * 2;
            float c0 = acc[mf][nf][0], c1 = acc[mf][nf][1];
            float c2 = acc[mf][nf][2], c3 = acc[mf][nf][3];
            if (act) {
                c0 = 1.0f / (1.0f + __expf(-c0));
                c1 = 1.0f / (1.0f + __expf(-c1));
                c2 = 1.0f / (1.0f + __expf(-c2));
                c3 = 1.0f / (1.0f + __expf(-c3));
            }
            *(float2*)(Out + r0 * 256 + col)       = make_float2(c0, c1);
            *(float2*)(Out + (r0 + 8) * 256 + col) = make_float2(c2, c3);
        }
    }
}

// ---------------- 4) WKV chunk-parallel scan ---------------------------------
__device__ __forceinline__ void wkv_state(float kt, float vt, float wdec,
                                          float& a, float& b, float& pp)
{
    float ww2 = pp + wdec;
    float d2  = ww2 - kt;
    float f   = __expf(-fabsf(d2));
    float f1  = (d2 >= 0.f) ? 1.f : f;
    float f2  = (d2 >= 0.f) ? f : 1.f;
    a  = f1 * a + f2 * vt;
    b  = f1 * b + f2;
    pp = fmaxf(ww2, kt);
}

__global__ __launch_bounds__(256) void wkv_pass1(const float* __restrict__ sd)
{
    int g     = blockIdx.x * 256 + threadIdx.x;
    int chain = g & (NCHAIN - 1);
    int chunk = g >> 12;
    int b = chain >> 9;
    int d = chain & 511;
    int c = d & 255;
    bool second = d >= 256;

    float wdec = -__expf(sd[d] * (1.0f / (float)TT));
    const size_t base = (size_t)b * TT * CC + c;

    float a = 0.f, bb = 0.f, pp = -1e38f;
    int tstart = chunk * CHLEN;

    for (int t0 = tstart; t0 < tstart + CHLEN; t0 += 8) {
        float kb[8], vb[8];
        #pragma unroll
        for (int i = 0; i < 8; i++) {
            int t  = t0 + i;
            int ti = second ? (((t & 63) << 6) | (t >> 6)) : t;
            size_t off = base + (size_t)ti * CC;
            kb[i] = g_k[off];
            vb[i] = g_v[off];
        }
        #pragma unroll
        for (int i = 0; i < 8; i++)
            wkv_state(kb[i], vb[i], wdec, a, bb, pp);
    }
    g_sa[chunk * NCHAIN + chain] = a;
    g_sb[chunk * NCHAIN + chain] = bb;
    g_sp[chunk * NCHAIN + chain] = pp;
}

__global__ __launch_bounds__(256) void wkv_pass2(const float* __restrict__ sd)
{
    int chain = blockIdx.x * 256 + threadIdx.x;
    int d = chain & 511;
    float wdec = -__expf(sd[d] * (1.0f / (float)TT));
    float Lw = (float)CHLEN * wdec;

    float A = 0.f, B = 0.f, P = -1e38f;
    for (int j = 0; j < NCHUNK; j++) {
        g_pa[j * NCHAIN + chain] = A;
        g_pb[j * NCHAIN + chain] = B;
        g_pp[j * NCHAIN + chain] = P;
        float ca = g_sa[j * NCHAIN + chain];
        float cb = g_sb[j * NCHAIN + chain];
        float cp = g_sp[j * NCHAIN + chain];
        float np = P + Lw;
        float p  = fmaxf(np, cp);
        float e1 = __expf(np - p);
        float e2 = __expf(cp - p);
        A = e1 * A + e2 * ca;
        B = e1 * B + e2 * cb;
        P = p;
    }
}

__global__ __launch_bounds__(256) void wkv_pass3(const float* __restrict__ sd,
                                                 const float* __restrict__ sf)
{
    int g     = blockIdx.x * 256 + threadIdx.x;
    int chain = g & (NCHAIN - 1);
    int chunk = g >> 12;
    int b = chain >> 9;
    int d = chain & 511;
    int c = d & 255;
    bool second = d >= 256;

    float wdec = -__expf(sd[d] * (1.0f / (float)TT));
    float u    =  sf[d] * (1.0f / (float)TT);

    const size_t base = (size_t)b * TT * CC + c;
    float* xsp = g_xs + (size_t)b * TT * DD + d;

    float a  = g_pa[chunk * NCHAIN + chain];
    float bb = g_pb[chunk * NCHAIN + chain];
    float pp = g_pp[chunk * NCHAIN + chain];

    int tstart = chunk * CHLEN;
    for (int t0 = tstart; t0 < tstart + CHLEN; t0 += 8) {
        float kb[8], vb[8], sb[8];
        #pragma unroll
        for (int i = 0; i < 8; i++) {
            int t  = t0 + i;
            int ti = second ? (((t & 63) << 6) | (t >> 6)) : t;
            size_t off = base + (size_t)ti * CC;
            kb[i] = g_k[off];
            vb[i] = g_v[off];
            sb[i] = g_sr[base + (size_t)t * CC];
        }
        #pragma unroll
        for (int i = 0; i < 8; i++) {
            float kt = kb[i], vt = vb[i];
            float ww = u + kt;
            float d1 = pp - ww;
            float e  = __expf(-fabsf(d1));
            float e1 = (d1 >= 0.f) ? 1.f : e;
            float e2 = (d1 >= 0.f) ? e : 1.f;
            float out = __fdividef(e1 * a + e2 * vt, e1 * bb + e2);
            wkv_state(kt, vt, wdec, a, bb, pp);
            xsp[(size_t)(t0 + i) * DD] = rnd_tf32(out * sb[i]);
        }
    }
}

// ---------------- launch -----------------------------------------------------
extern "C" void kernel_launch(void* const* d_in, const int* in_sizes, int n_in,
                              void* d_out, int out_size)
{
    const float* x     = (const float*)d_in[0];
    const float* alpha = (const float*)d_in[1];
    const float* cw1   = (const float*)d_in[2];
    const float* cw3   = (const float*)d_in[3];
    const float* cw5   = (const float*)d_in[4];
    const float* Wk    = (const float*)d_in[5];
    const float* Wv    = (const float*)d_in[6];
    const float* Wr    = (const float*)d_in[7];
    const float* Wo    = (const float*)d_in[8];
    const float* sd    = (const float*)d_in[9];
    const float* sf    = (const float*)d_in[10];

    float *xf, *k, *v, *sr, *xs, *wk, *wv, *wr, *wo;
    cudaGetSymbolAddress((void**)&xf, g_xf);
    cudaGetSymbolAddress((void**)&k,  g_k);
    cudaGetSymbolAddress((void**)&v,  g_v);
    cudaGetSymbolAddress((void**)&sr, g_sr);
    cudaGetSymbolAddress((void**)&xs, g_xs);
    cudaGetSymbolAddress((void**)&wk, g_wk);
    cudaGetSymbolAddress((void**)&wv, g_wv);
    cudaGetSymbolAddress((void**)&wr, g_wr);
    cudaGetSymbolAddress((void**)&wo, g_wo);

    cudaFuncSetAttribute(gemm_qkv_kernel,
                         cudaFuncAttributeMaxDynamicSharedMemorySize, GS_BYTES);

    round_weights_kernel<<<(CC * DD + 255) / 256, 256>>>(Wk, Wv, Wr, Wo);
    combine_weights_kernel<<<1, 256>>>(alpha, cw1, cw3, cw5);
    omni_conv_kernel<<<BATCH * WW_, 256>>>(x);

    // fused k / v / r(sigmoid) gemms: grid.x = 6 (3 groups x 2 n-blocks)
    dim3 g3(6, MM / 128);
    gemm_qkv_kernel<<<g3, 128, GS_BYTES>>>(xf, wk, wv, wr, k, v, sr, CC, 4);

    wkv_pass1<<<(NCHAIN * NCHUNK) / 256, 256>>>(sd);
    wkv_pass2<<<NCHAIN / 256, 256>>>(sd);
    wkv_pass3<<<(NCHAIN * NCHUNK) / 256, 256>>>(sd, sf);

    // output projection: grid.x = 2 (group 0 only)
    dim3 g1(2, MM / 128);
    gemm_qkv_kernel<<<g1, 128, GS_BYTES>>>(xs, wo, wo, wo,
                                           (float*)d_out, (float*)d_out,
                                           (float*)d_out, DD, 0);
}

// round 12
// speedup vs baseline: 1.1597x; 1.1597x over previous
#include <cuda_runtime.h>
#include <cstdint>

#define BATCH 8
#define HH    64
#define WW_   64
#define TT    4096
#define CC    256
#define DD    512
#define MM    (BATCH * TT)   // 32768

#define NCHAIN 4096
#define NCHUNK 32
#define CHLEN  128

// ---------------- scratch (static device globals; no runtime alloc) ----------
__device__ float g_comb[25 * CC];
__device__ float g_xf[BATCH * TT * CC];     // tf32-rounded activations
__device__ float g_k [BATCH * TT * CC];
__device__ float g_v [BATCH * TT * CC];
__device__ float g_sr[BATCH * TT * CC];
__device__ float g_xs[BATCH * TT * DD];     // tf32-rounded scan output
__device__ float g_sa[NCHUNK * NCHAIN];
__device__ float g_sb[NCHUNK * NCHAIN];
__device__ float g_sp[NCHUNK * NCHAIN];
__device__ float g_pa[NCHUNK * NCHAIN];
__device__ float g_pb[NCHUNK * NCHAIN];
__device__ float g_pp[NCHUNK * NCHAIN];
// tf32-rounded weights
__device__ float g_wk[CC * CC];
__device__ float g_wv[CC * CC];
__device__ float g_wr[CC * CC];
__device__ float g_wo[CC * DD];

__device__ __forceinline__ unsigned f2tf32(float f) {
    unsigned u;
    asm("cvt.rna.tf32.f32 %0, %1;" : "=r"(u) : "f"(f));
    return u;
}
__device__ __forceinline__ float rnd_tf32(float f) {
    return __uint_as_float(f2tf32(f));
}
__device__ __forceinline__ uint32_t smem_u32(const void* p) {
    uint32_t a;
    asm("{ .reg .u64 t; cvta.to.shared.u64 t, %1; cvt.u32.u64 %0, t; }"
        : "=r"(a) : "l"(p));
    return a;
}
__device__ __forceinline__ void cp16(uint32_t dst, const void* src) {
    asm volatile("cp.async.ca.shared.global [%0], [%1], 16;" :: "r"(dst), "l"(src));
}
#define CP_COMMIT() asm volatile("cp.async.commit_group;" ::: "memory")
#define CP_WAIT1()  asm volatile("cp.async.wait_group 1;"  ::: "memory")

// ---------------- 0) round weights to tf32 grid ------------------------------
__global__ void round_weights_kernel(const float* __restrict__ Wk,
                                     const float* __restrict__ Wv,
                                     const float* __restrict__ Wr,
                                     const float* __restrict__ Wo)
{
    int i = blockIdx.x * 256 + threadIdx.x;
    if (i < CC * CC) {
        g_wk[i] = rnd_tf32(Wk[i]);
        g_wv[i] = rnd_tf32(Wv[i]);
        g_wr[i] = rnd_tf32(Wr[i]);
    }
    if (i < CC * DD) g_wo[i] = rnd_tf32(Wo[i]);
}

// ---------------- 1) combine identity + 1x1 + 3x3 + 5x5 into one 5x5 ---------
__global__ void combine_weights_kernel(const float* __restrict__ alpha,
                                       const float* __restrict__ cw1,
                                       const float* __restrict__ cw3,
                                       const float* __restrict__ cw5)
{
    int c = threadIdx.x;
    float a0 = alpha[0], a1 = alpha[1], a2 = alpha[2], a3 = alpha[3];
    #pragma unroll
    for (int j = 0; j < 5; j++) {
        #pragma unroll
        for (int i = 0; i < 5; i++) {
            float v = a3 * cw5[c * 25 + j * 5 + i];
            if (j >= 1 && j <= 3 && i >= 1 && i <= 3)
                v += a2 * cw3[c * 9 + (j - 1) * 3 + (i - 1)];
            if (j == 2 && i == 2)
                v += a1 * cw1[c] + a0;
            g_comb[(j * 5 + i) * CC + c] = v;
        }
    }
}

// ---------------- 2) depthwise 5x5 conv, 2 output columns per block ----------
// Window win[5][6] shared by two adjacent x-columns: 6 loads per 2 outputs.
__global__ __launch_bounds__(256) void omni_conv_kernel(const float* __restrict__ x)
{
    int b   = blockIdx.x >> 5;
    int xp  = blockIdx.x & 31;
    int xc0 = xp * 2;
    int c   = threadIdx.x;

    float wgt[25];
    #pragma unroll
    for (int j = 0; j < 25; j++) wgt[j] = g_comb[j * CC + c];

    const float* xin  = x    + (size_t)b * TT * CC + c;
    float*       xout = g_xf + (size_t)b * TT * CC + (size_t)xc0 * CC + c;

    float win[5][6];
    #pragma unroll
    for (int i = 0; i < 6; i++) { win[0][i] = 0.f; win[1][i] = 0.f; }
    #pragma unroll
    for (int r = 0; r < 3; r++) {
        #pragma unroll
        for (int i = 0; i < 6; i++) {
            int xx = xc0 - 2 + i;
            win[2 + r][i] = (xx >= 0 && xx < WW_) ? xin[((size_t)r * WW_ + xx) * CC] : 0.f;
        }
    }

    #pragma unroll 2
    for (int y = 0; y < HH; y++) {
        float acc0 = 0.f, acc1 = 0.f;
        #pragma unroll
        for (int j = 0; j < 5; j++)
            #pragma unroll
            for (int i = 0; i < 5; i++) {
                acc0 = fmaf(wgt[j * 5 + i], win[j][i],     acc0);
                acc1 = fmaf(wgt[j * 5 + i], win[j][i + 1], acc1);
            }
        xout[(size_t)y * WW_ * CC]      = rnd_tf32(acc0);
        xout[(size_t)y * WW_ * CC + CC] = rnd_tf32(acc1);

        #pragma unroll
        for (int j = 0; j < 4; j++)
            #pragma unroll
            for (int i = 0; i < 6; i++) win[j][i] = win[j + 1][i];
        int row = y + 3;
        #pragma unroll
        for (int i = 0; i < 6; i++) {
            int xx = xc0 - 2 + i;
            win[4][i] = (row < HH && xx >= 0 && xx < WW_)
                        ? xin[((size_t)row * WW_ + xx) * CC] : 0.f;
        }
    }
}

// ---------------- 3) tf32 mma.sync GEMM: 128x64 block, 4 CTAs/SM -------------
// Inputs pre-rounded to tf32 grid -> HW truncation in mma == rna (bit-identical).
// 128 threads = 4 warps (2M x 2N), warp tile 64x32 (the proven R7 shape).
// cp.async 2-stage pipeline, smem 55296 B/CTA -> 4 CTAs/SM, 4 independent
// barrier groups for latency hiding (vs 2x8-warp monoliths).
#define AW    (128 * 36)                    // A-stage words
#define BW    (64 * 36)                     // B-stage words
#define STW   (AW + BW)                     // words per stage
#define GS_BYTES (2 * STW * 4)              // 55296

__global__ __launch_bounds__(128, 4) void gemm_qkv_kernel(
    const float* __restrict__ A,
    const float* __restrict__ W0, const float* __restrict__ W1,
    const float* __restrict__ W2,
    float* __restrict__ O0, float* __restrict__ O1, float* __restrict__ O2,
    int K, int actsel)
{
    extern __shared__ unsigned gsm[];
    const uint32_t smb = smem_u32(gsm);
    const int tid = threadIdx.x;
    const int grp = blockIdx.x >> 2;               // 0..2 (weight/output select)
    const int bn  = (blockIdx.x & 3) * 64;
    const float* W   = (grp == 0) ? W0 : (grp == 1) ? W1 : W2;
    float*       Out = (grp == 0) ? O0 : (grp == 1) ? O1 : O2;
    const int act = (actsel >> grp) & 1;
    const size_t bm = (size_t)blockIdx.y * 128;

    const int lane = tid & 31, wid = tid >> 5;
    const int wm = (wid & 1) * 64;
    const int wn = (wid >> 1) * 32;
    const int qr = lane >> 2;
    const int qc = lane & 3;

    // cp.async staging: A -> thread t owns row t (8 cp16); B -> row t>>1, half t&1 (4 cp16)
    const float* Ag = A + (bm + tid) * (size_t)K;
    const float* Bg = W + (size_t)(bn + (tid >> 1)) * K + (tid & 1) * 16;
    const uint32_t dAb = smb + (uint32_t)(tid * 36) * 4;
    const uint32_t dBb = smb + (uint32_t)(AW + (tid >> 1) * 36 + (tid & 1) * 16) * 4;

    const int NT = K >> 5;

    float acc[4][4][4];
    #pragma unroll
    for (int mf = 0; mf < 4; mf++)
        #pragma unroll
        for (int nf = 0; nf < 4; nf++)
            #pragma unroll
            for (int i = 0; i < 4; i++) acc[mf][nf][i] = 0.f;

    // prologue: stages 0 and 1 in flight
    #pragma unroll
    for (int s = 0; s < 2; s++) {
        uint32_t da = dAb + (uint32_t)(s * STW) * 4;
        uint32_t db = dBb + (uint32_t)(s * STW) * 4;
        const float* a = Ag + s * 32;
        const float* w = Bg + s * 32;
        #pragma unroll
        for (int j = 0; j < 8; j++) cp16(da + j * 16, a + j * 4);
        #pragma unroll
        for (int j = 0; j < 4; j++) cp16(db + j * 16, w + j * 4);
        CP_COMMIT();
    }

    for (int kt = 0; kt < NT; kt++) {
        CP_WAIT1();
        __syncthreads();

        const unsigned (*As)[36] = (const unsigned (*)[36])(gsm + (kt & 1) * STW);
        const unsigned (*Ws)[36] = (const unsigned (*)[36])(gsm + (kt & 1) * STW + AW);

        #pragma unroll
        for (int k8 = 0; k8 < 4; k8++) {
            const int kc = k8 * 8;
            unsigned b0[4], b1[4];
            #pragma unroll
            for (int nf = 0; nf < 4; nf++) {
                int n = wn + nf * 8 + qr;
                b0[nf] = Ws[n][kc + qc];
                b1[nf] = Ws[n][kc + qc + 4];
            }
            #pragma unroll
            for (int mf = 0; mf < 4; mf++) {
                int r0 = wm + mf * 16 + qr;
                unsigned a0 = As[r0][kc + qc];
                unsigned a1 = As[r0 + 8][kc + qc];
                unsigned a2 = As[r0][kc + qc + 4];
                unsigned a3 = As[r0 + 8][kc + qc + 4];
                #pragma unroll
                for (int nf = 0; nf < 4; nf++) {
                    asm volatile(
                        "mma.sync.aligned.m16n8k8.row.col.f32.tf32.tf32.f32 "
                        "{%0,%1,%2,%3}, {%4,%5,%6,%7}, {%8,%9}, {%0,%1,%2,%3};"
                        : "+f"(acc[mf][nf][0]), "+f"(acc[mf][nf][1]),
                          "+f"(acc[mf][nf][2]), "+f"(acc[mf][nf][3])
                        : "r"(a0), "r"(a1), "r"(a2), "r"(a3),
                          "r"(b0[nf]), "r"(b1[nf]));
                }
            }
        }
        __syncthreads();     // all warps done reading this stage

        if (kt + 2 < NT) {
            uint32_t da = dAb + (uint32_t)((kt & 1) * STW) * 4;
            uint32_t db = dBb + (uint32_t)((kt & 1) * STW) * 4;
            const float* a = Ag + (kt + 2) * 32;
            const float* w = Bg + (kt + 2) * 32;
            #pragma unroll
            for (int j = 0; j < 8; j++) cp16(da + j * 16, a + j * 4);
            #pragma unroll
            for (int j = 0; j < 4; j++) cp16(db + j * 16, w + j * 4);
        }
        CP_COMMIT();
    }

    #pragma unroll
    for (int mf = 0; mf < 4; mf++) {
        size_t r0 = bm + wm + mf * 16 + qr;
        #pragma unroll
        for (int nf = 0; nf < 4; nf++) {
            int col = bn + wn + nf * 8 + qc * 2;
            float c0 = acc[mf][nf][0], c1 = acc[mf][nf][1];
            float c2 = acc[mf][nf][2], c3 = acc[mf][nf][3];
            if (act) {
                c0 = 1.0f / (1.0f + __expf(-c0));
                c1 = 1.0f / (1.0f + __expf(-c1));
                c2 = 1.0f / (1.0f + __expf(-c2));
                c3 = 1.0f / (1.0f + __expf(-c3));
            }
            *(float2*)(Out + r0 * 256 + col)       = make_float2(c0, c1);
            *(float2*)(Out + (r0 + 8) * 256 + col) = make_float2(c2, c3);
        }
    }
}

// ---------------- 4) WKV chunk-parallel scan ---------------------------------
__device__ __forceinline__ void wkv_state(float kt, float vt, float wdec,
                                          float& a, float& b, float& pp)
{
    float ww2 = pp + wdec;
    float d2  = ww2 - kt;
    float f   = __expf(-fabsf(d2));
    float f1  = (d2 >= 0.f) ? 1.f : f;
    float f2  = (d2 >= 0.f) ? f : 1.f;
    a  = f1 * a + f2 * vt;
    b  = f1 * b + f2;
    pp = fmaxf(ww2, kt);
}

__global__ __launch_bounds__(256) void wkv_pass1(const float* __restrict__ sd)
{
    int g     = blockIdx.x * 256 + threadIdx.x;
    int chain = g & (NCHAIN - 1);
    int chunk = g >> 12;
    int b = chain >> 9;
    int d = chain & 511;
    int c = d & 255;
    bool second = d >= 256;

    float wdec = -__expf(sd[d] * (1.0f / (float)TT));
    const size_t base = (size_t)b * TT * CC + c;

    float a = 0.f, bb = 0.f, pp = -1e38f;
    int tstart = chunk * CHLEN;

    for (int t0 = tstart; t0 < tstart + CHLEN; t0 += 8) {
        float kb[8], vb[8];
        #pragma unroll
        for (int i = 0; i < 8; i++) {
            int t  = t0 + i;
            int ti = second ? (((t & 63) << 6) | (t >> 6)) : t;
            size_t off = base + (size_t)ti * CC;
            kb[i] = g_k[off];
            vb[i] = g_v[off];
        }
        #pragma unroll
        for (int i = 0; i < 8; i++)
            wkv_state(kb[i], vb[i], wdec, a, bb, pp);
    }
    g_sa[chunk * NCHAIN + chain] = a;
    g_sb[chunk * NCHAIN + chain] = bb;
    g_sp[chunk * NCHAIN + chain] = pp;
}

__global__ __launch_bounds__(256) void wkv_pass2(const float* __restrict__ sd)
{
    int chain = blockIdx.x * 256 + threadIdx.x;
    int d = chain & 511;
    float wdec = -__expf(sd[d] * (1.0f / (float)TT));
    float Lw = (float)CHLEN * wdec;

    float A = 0.f, B = 0.f, P = -1e38f;
    for (int j = 0; j < NCHUNK; j++) {
        g_pa[j * NCHAIN + chain] = A;
        g_pb[j * NCHAIN + chain] = B;
        g_pp[j * NCHAIN + chain] = P;
        float ca = g_sa[j * NCHAIN + chain];
        float cb = g_sb[j * NCHAIN + chain];
        float cp = g_sp[j * NCHAIN + chain];
        float np = P + Lw;
        float p  = fmaxf(np, cp);
        float e1 = __expf(np - p);
        float e2 = __expf(cp - p);
        A = e1 * A + e2 * ca;
        B = e1 * B + e2 * cb;
        P = p;
    }
}

__global__ __launch_bounds__(256) void wkv_pass3(const float* __restrict__ sd,
                                                 const float* __restrict__ sf)
{
    int g     = blockIdx.x * 256 + threadIdx.x;
    int chain = g & (NCHAIN - 1);
    int chunk = g >> 12;
    int b = chain >> 9;
    int d = chain & 511;
    int c = d & 255;
    bool second = d >= 256;

    float wdec = -__expf(sd[d] * (1.0f / (float)TT));
    float u    =  sf[d] * (1.0f / (float)TT);

    const size_t base = (size_t)b * TT * CC + c;
    float* xsp = g_xs + (size_t)b * TT * DD + d;

    float a  = g_pa[chunk * NCHAIN + chain];
    float bb = g_pb[chunk * NCHAIN + chain];
    float pp = g_pp[chunk * NCHAIN + chain];

    int tstart = chunk * CHLEN;
    for (int t0 = tstart; t0 < tstart + CHLEN; t0 += 8) {
        float kb[8], vb[8], sb[8];
        #pragma unroll
        for (int i = 0; i < 8; i++) {
            int t  = t0 + i;
            int ti = second ? (((t & 63) << 6) | (t >> 6)) : t;
            size_t off = base + (size_t)ti * CC;
            kb[i] = g_k[off];
            vb[i] = g_v[off];
            sb[i] = g_sr[base + (size_t)t * CC];
        }
        #pragma unroll
        for (int i = 0; i < 8; i++) {
            float kt = kb[i], vt = vb[i];
            float ww = u + kt;
            float d1 = pp - ww;
            float e  = __expf(-fabsf(d1));
            float e1 = (d1 >= 0.f) ? 1.f : e;
            float e2 = (d1 >= 0.f) ? e : 1.f;
            float out = __fdividef(e1 * a + e2 * vt, e1 * bb + e2);
            wkv_state(kt, vt, wdec, a, bb, pp);
            xsp[(size_t)(t0 + i) * DD] = rnd_tf32(out * sb[i]);
        }
    }
}

// ---------------- launch -----------------------------------------------------
extern "C" void kernel_launch(void* const* d_in, const int* in_sizes, int n_in,
                              void* d_out, int out_size)
{
    const float* x     = (const float*)d_in[0];
    const float* alpha = (const float*)d_in[1];
    const float* cw1   = (const float*)d_in[2];
    const float* cw3   = (const float*)d_in[3];
    const float* cw5   = (const float*)d_in[4];
    const float* Wk    = (const float*)d_in[5];
    const float* Wv    = (const float*)d_in[6];
    const float* Wr    = (const float*)d_in[7];
    const float* Wo    = (const float*)d_in[8];
    const float* sd    = (const float*)d_in[9];
    const float* sf    = (const float*)d_in[10];

    float *xf, *k, *v, *sr, *xs, *wk, *wv, *wr, *wo;
    cudaGetSymbolAddress((void**)&xf, g_xf);
    cudaGetSymbolAddress((void**)&k,  g_k);
    cudaGetSymbolAddress((void**)&v,  g_v);
    cudaGetSymbolAddress((void**)&sr, g_sr);
    cudaGetSymbolAddress((void**)&xs, g_xs);
    cudaGetSymbolAddress((void**)&wk, g_wk);
    cudaGetSymbolAddress((void**)&wv, g_wv);
    cudaGetSymbolAddress((void**)&wr, g_wr);
    cudaGetSymbolAddress((void**)&wo, g_wo);

    cudaFuncSetAttribute(gemm_qkv_kernel,
                         cudaFuncAttributeMaxDynamicSharedMemorySize, GS_BYTES);

    round_weights_kernel<<<(CC * DD + 255) / 256, 256>>>(Wk, Wv, Wr, Wo);
    combine_weights_kernel<<<1, 256>>>(alpha, cw1, cw3, cw5);
    omni_conv_kernel<<<BATCH * 32, 256>>>(x);

    // fused k / v / r(sigmoid) gemms: grid.x = 12 (3 groups x 4 n-blocks of 64)
    dim3 g3(12, MM / 128);
    gemm_qkv_kernel<<<g3, 128, GS_BYTES>>>(xf, wk, wv, wr, k, v, sr, CC, 4);

    wkv_pass1<<<(NCHAIN * NCHUNK) / 256, 256>>>(sd);
    wkv_pass2<<<NCHAIN / 256, 256>>>(sd);
    wkv_pass3<<<(NCHAIN * NCHUNK) / 256, 256>>>(sd, sf);

    // output projection: grid.x = 4 (group 0 only), K = 512
    dim3 g1(4, MM / 128);
    gemm_qkv_kernel<<<g1, 128, GS_BYTES>>>(xs, wo, wo, wo,
                                           (float*)d_out, (float*)d_out,
                                           (float*)d_out, DD, 0);
}

// round 13
// speedup vs baseline: 1.4046x; 1.2111x over previous
#include <cuda_runtime.h>
#include <cstdint>

#define BATCH 8
#define HH    64
#define WW_   64
#define TT    4096
#define CC    256
#define DD    512
#define MM    (BATCH * TT)   // 32768

#define NCHAIN 4096
#define NCHUNK 32
#define CHLEN  128

// ---------------- scratch (static device globals; no runtime alloc) ----------
__device__ float g_comb[25 * CC];
__device__ float g_xf[BATCH * TT * CC];     // tf32-rounded activations
__device__ float g_k [BATCH * TT * CC];
__device__ float g_v [BATCH * TT * CC];
__device__ float g_sr[BATCH * TT * CC];
__device__ float g_xs[BATCH * TT * DD];     // tf32-rounded scan output
__device__ float g_sa[NCHUNK * NCHAIN];
__device__ float g_sb[NCHUNK * NCHAIN];
__device__ float g_sp[NCHUNK * NCHAIN];
__device__ float g_pa[NCHUNK * NCHAIN];
__device__ float g_pb[NCHUNK * NCHAIN];
__device__ float g_pp[NCHUNK * NCHAIN];
// tf32-rounded weights
__device__ float g_wk[CC * CC];
__device__ float g_wv[CC * CC];
__device__ float g_wr[CC * CC];
__device__ float g_wo[CC * DD];

__device__ __forceinline__ unsigned f2tf32(float f) {
    unsigned u;
    asm("cvt.rna.tf32.f32 %0, %1;" : "=r"(u) : "f"(f));
    return u;
}
__device__ __forceinline__ float rnd_tf32(float f) {
    return __uint_as_float(f2tf32(f));
}

// ---------------- 0) round weights to tf32 grid ------------------------------
__global__ void round_weights_kernel(const float* __restrict__ Wk,
                                     const float* __restrict__ Wv,
                                     const float* __restrict__ Wr,
                                     const float* __restrict__ Wo)
{
    int i = blockIdx.x * 256 + threadIdx.x;
    if (i < CC * CC) {
        g_wk[i] = rnd_tf32(Wk[i]);
        g_wv[i] = rnd_tf32(Wv[i]);
        g_wr[i] = rnd_tf32(Wr[i]);
    }
    if (i < CC * DD) g_wo[i] = rnd_tf32(Wo[i]);
}

// ---------------- 1) combine identity + 1x1 + 3x3 + 5x5 into one 5x5 ---------
__global__ void combine_weights_kernel(const float* __restrict__ alpha,
                                       const float* __restrict__ cw1,
                                       const float* __restrict__ cw3,
                                       const float* __restrict__ cw5)
{
    int c = threadIdx.x;
    float a0 = alpha[0], a1 = alpha[1], a2 = alpha[2], a3 = alpha[3];
    #pragma unroll
    for (int j = 0; j < 5; j++) {
        #pragma unroll
        for (int i = 0; i < 5; i++) {
            float v = a3 * cw5[c * 25 + j * 5 + i];
            if (j >= 1 && j <= 3 && i >= 1 && i <= 3)
                v += a2 * cw3[c * 9 + (j - 1) * 3 + (i - 1)];
            if (j == 2 && i == 2)
                v += a1 * cw1[c] + a0;
            g_comb[(j * 5 + i) * CC + c] = v;
        }
    }
}

// ---------------- 2) depthwise 5x5 conv, 2 output columns per block ----------
__global__ __launch_bounds__(256) void omni_conv_kernel(const float* __restrict__ x)
{
    int b   = blockIdx.x >> 5;
    int xp  = blockIdx.x & 31;
    int xc0 = xp * 2;
    int c   = threadIdx.x;

    float wgt[25];
    #pragma unroll
    for (int j = 0; j < 25; j++) wgt[j] = g_comb[j * CC + c];

    const float* xin  = x    + (size_t)b * TT * CC + c;
    float*       xout = g_xf + (size_t)b * TT * CC + (size_t)xc0 * CC + c;

    float win[5][6];
    #pragma unroll
    for (int i = 0; i < 6; i++) { win[0][i] = 0.f; win[1][i] = 0.f; }
    #pragma unroll
    for (int r = 0; r < 3; r++) {
        #pragma unroll
        for (int i = 0; i < 6; i++) {
            int xx = xc0 - 2 + i;
            win[2 + r][i] = (xx >= 0 && xx < WW_) ? xin[((size_t)r * WW_ + xx) * CC] : 0.f;
        }
    }

    #pragma unroll 2
    for (int y = 0; y < HH; y++) {
        float acc0 = 0.f, acc1 = 0.f;
        #pragma unroll
        for (int j = 0; j < 5; j++)
            #pragma unroll
            for (int i = 0; i < 5; i++) {
                acc0 = fmaf(wgt[j * 5 + i], win[j][i],     acc0);
                acc1 = fmaf(wgt[j * 5 + i], win[j][i + 1], acc1);
            }
        xout[(size_t)y * WW_ * CC]      = rnd_tf32(acc0);
        xout[(size_t)y * WW_ * CC + CC] = rnd_tf32(acc1);

        #pragma unroll
        for (int j = 0; j < 4; j++)
            #pragma unroll
            for (int i = 0; i < 6; i++) win[j][i] = win[j + 1][i];
        int row = y + 3;
        #pragma unroll
        for (int i = 0; i < 6; i++) {
            int xx = xc0 - 2 + i;
            win[4][i] = (row < HH && xx >= 0 && xx < WW_)
                        ? xin[((size_t)row * WW_ + xx) * CC] : 0.f;
        }
    }
}

// ---------------- 3) tf32 mma.sync GEMM, paired-column layout ----------------
// Inputs pre-rounded to tf32 grid -> HW truncation in mma == rna (bit-identical).
// Block 128x128x32, 8 warps (2x4), warp tile 64x32 (proven R7 shape).
// Per-k8 column order [0,4,1,5,2,6,3,7]: fragment pair (qc, qc+4) is 8B-
// adjacent -> one LDS.64 per pair (12 LDS.64 per warp-k8 vs 24 LDS.32).
// Chunk XOR  chunk(r,k8,u) = 2*(k8^(r&3)) + (u ^ (k8>>1) ^ ((r>>2)&1))
// makes STS.128 stores AND LDS.64 frag loads bank-conflict-free (verified
// lane-by-lane: each 128B phase covers all 32 banks exactly once).
// Row stride 32 words (no padding). 2 stages x (A+B) = 64KB -> 2 CTAs/SM.
#define STW      (128 * 32)                 // words per matrix per stage
#define GS_BYTES (4 * STW * 4)              // 65536

__device__ __forceinline__ void stage_store(unsigned* __restrict__ dst,
                                            int row, int h,
                                            const float* __restrict__ f)
{
    const int rb   = row * 32;
    const int p    = row & 3;
    const int beta = (row >> 2) & 1;
    #pragma unroll
    for (int j = 0; j < 2; j++) {
        const int k8 = 2 * h + j;
        const int cb = 2 * (k8 ^ p);
        const int gb = h ^ beta;             // (k8>>1) == h
        const int b  = j * 8;
        uint4 v0, v1;
        v0.x = __float_as_uint(f[b + 0]); v0.y = __float_as_uint(f[b + 4]);
        v0.z = __float_as_uint(f[b + 1]); v0.w = __float_as_uint(f[b + 5]);
        v1.x = __float_as_uint(f[b + 2]); v1.y = __float_as_uint(f[b + 6]);
        v1.z = __float_as_uint(f[b + 3]); v1.w = __float_as_uint(f[b + 7]);
        *(uint4*)&dst[rb + (cb + (0 ^ gb)) * 4] = v0;
        *(uint4*)&dst[rb + (cb + (1 ^ gb)) * 4] = v1;
    }
}

__global__ __launch_bounds__(256, 2) void gemm_qkv_kernel(
    const float* __restrict__ A,
    const float* __restrict__ W0, const float* __restrict__ W1,
    const float* __restrict__ W2,
    float* __restrict__ O0, float* __restrict__ O1, float* __restrict__ O2,
    int K, int actsel)
{
    extern __shared__ unsigned gsm[];
    const int tid = threadIdx.x;
    const int grp = blockIdx.x >> 1;               // 0..2 weight/output select
    const int bn  = (blockIdx.x & 1) * 128;
    const float* W   = (grp == 0) ? W0 : (grp == 1) ? W1 : W2;
    float*       Out = (grp == 0) ? O0 : (grp == 1) ? O1 : O2;
    const int act = (actsel >> grp) & 1;
    const size_t bm = (size_t)blockIdx.y * 128;

    const int lane = tid & 31, wid = tid >> 5;
    const int wm = (wid & 1) * 64;
    const int wn = (wid >> 1) * 32;
    const int qr = lane >> 2;
    const int qc = lane & 3;
    const int u  = qc >> 1;
    const int wq = 2 * (qc & 1);

    // staging: thread -> row (0..127) + k-half (16 cols) of both tiles
    const int srow = tid >> 1;
    const int sh   = tid & 1;
    const float* Ag = A + (bm + srow) * (size_t)K + sh * 16;
    const float* Wg = W + (size_t)(bn + srow) * K + sh * 16;

    const int NT = K >> 5;

    float acc[4][4][4];
    #pragma unroll
    for (int mf = 0; mf < 4; mf++)
        #pragma unroll
        for (int nf = 0; nf < 4; nf++)
            #pragma unroll
            for (int i = 0; i < 4; i++) acc[mf][nf][i] = 0.f;

    float fa[16], fw[16];

    // prologue: load + stage ktile 0
    #pragma unroll
    for (int j = 0; j < 4; j++) {
        *(float4*)&fa[j * 4] = *(const float4*)(Ag + j * 4);
        *(float4*)&fw[j * 4] = *(const float4*)(Wg + j * 4);
    }
    stage_store(gsm,       srow, sh, fa);
    stage_store(gsm + STW, srow, sh, fw);
    __syncthreads();

    for (int kt = 0; kt < NT; kt++) {
        const bool more = (kt + 1 < NT);
        if (more) {
            const float* a = Ag + (kt + 1) * 32;
            const float* w = Wg + (kt + 1) * 32;
            #pragma unroll
            for (int j = 0; j < 4; j++) {
                *(float4*)&fa[j * 4] = *(const float4*)(a + j * 4);
                *(float4*)&fw[j * 4] = *(const float4*)(w + j * 4);
            }
        }

        const unsigned* Asm = gsm + (kt & 1) * 2 * STW;
        const unsigned* Bsm = Asm + STW;

        #pragma unroll
        for (int k8 = 0; k8 < 4; k8++) {
            const int g = k8 >> 1;
            uint2 vb[4];
            #pragma unroll
            for (int nf = 0; nf < 4; nf++) {
                const int n = wn + nf * 8 + qr;
                const int ch = 2 * (k8 ^ (n & 3)) + (u ^ g ^ ((n >> 2) & 1));
                vb[nf] = *(const uint2*)&Bsm[n * 32 + ch * 4 + wq];
            }
            #pragma unroll
            for (int mf = 0; mf < 4; mf++) {
                const int r0 = wm + mf * 16 + qr;
                const int ch = 2 * (k8 ^ (r0 & 3)) + (u ^ g ^ ((r0 >> 2) & 1));
                // rows r0 and r0+8 share (r&3) and ((r>>2)&1) -> same chunk
                uint2 pl = *(const uint2*)&Asm[r0 * 32 + ch * 4 + wq];
                uint2 ph = *(const uint2*)&Asm[(r0 + 8) * 32 + ch * 4 + wq];
                #pragma unroll
                for (int nf = 0; nf < 4; nf++) {
                    asm volatile(
                        "mma.sync.aligned.m16n8k8.row.col.f32.tf32.tf32.f32 "
                        "{%0,%1,%2,%3}, {%4,%5,%6,%7}, {%8,%9}, {%0,%1,%2,%3};"
                        : "+f"(acc[mf][nf][0]), "+f"(acc[mf][nf][1]),
                          "+f"(acc[mf][nf][2]), "+f"(acc[mf][nf][3])
                        : "r"(pl.x), "r"(ph.x), "r"(pl.y), "r"(ph.y),
                          "r"(vb[nf].x), "r"(vb[nf].y));
                }
            }
        }

        if (more) {
            unsigned* AsmN = gsm + ((kt + 1) & 1) * 2 * STW;
            stage_store(AsmN,       srow, sh, fa);
            stage_store(AsmN + STW, srow, sh, fw);
        }
        __syncthreads();
    }

    #pragma unroll
    for (int mf = 0; mf < 4; mf++) {
        size_t r0 = bm + wm + mf * 16 + qr;
        #pragma unroll
        for (int nf = 0; nf < 4; nf++) {
            int col = bn + wn + nf * 8 + qc * 2;
            float c0 = acc[mf][nf][0], c1 = acc[mf][nf][1];
            float c2 = acc[mf][nf][2], c3 = acc[mf][nf][3];
            if (act) {
                c0 = 1.0f / (1.0f + __expf(-c0));
                c1 = 1.0f / (1.0f + __expf(-c1));
                c2 = 1.0f / (1.0f + __expf(-c2));
                c3 = 1.0f / (1.0f + __expf(-c3));
            }
            *(float2*)(Out + r0 * 256 + col)       = make_float2(c0, c1);
            *(float2*)(Out + (r0 + 8) * 256 + col) = make_float2(c2, c3);
        }
    }
}

// ---------------- 4) WKV chunk-parallel scan ---------------------------------
__device__ __forceinline__ void wkv_state(float kt, float vt, float wdec,
                                          float& a, float& b, float& pp)
{
    float ww2 = pp + wdec;
    float d2  = ww2 - kt;
    float f   = __expf(-fabsf(d2));
    float f1  = (d2 >= 0.f) ? 1.f : f;
    float f2  = (d2 >= 0.f) ? f : 1.f;
    a  = f1 * a + f2 * vt;
    b  = f1 * b + f2;
    pp = fmaxf(ww2, kt);
}

__global__ __launch_bounds__(256) void wkv_pass1(const float* __restrict__ sd)
{
    int g     = blockIdx.x * 256 + threadIdx.x;
    int chain = g & (NCHAIN - 1);
    int chunk = g >> 12;
    int b = chain >> 9;
    int d = chain & 511;
    int c = d & 255;
    bool second = d >= 256;

    float wdec = -__expf(sd[d] * (1.0f / (float)TT));
    const size_t base = (size_t)b * TT * CC + c;

    float a = 0.f, bb = 0.f, pp = -1e38f;
    int tstart = chunk * CHLEN;

    for (int t0 = tstart; t0 < tstart + CHLEN; t0 += 8) {
        float kb[8], vb[8];
        #pragma unroll
        for (int i = 0; i < 8; i++) {
            int t  = t0 + i;
            int ti = second ? (((t & 63) << 6) | (t >> 6)) : t;
            size_t off = base + (size_t)ti * CC;
            kb[i] = g_k[off];
            vb[i] = g_v[off];
        }
        #pragma unroll
        for (int i = 0; i < 8; i++)
            wkv_state(kb[i], vb[i], wdec, a, bb, pp);
    }
    g_sa[chunk * NCHAIN + chain] = a;
    g_sb[chunk * NCHAIN + chain] = bb;
    g_sp[chunk * NCHAIN + chain] = pp;
}

__global__ __launch_bounds__(256) void wkv_pass2(const float* __restrict__ sd)
{
    int chain = blockIdx.x * 256 + threadIdx.x;
    int d = chain & 511;
    float wdec = -__expf(sd[d] * (1.0f / (float)TT));
    float Lw = (float)CHLEN * wdec;

    float A = 0.f, B = 0.f, P = -1e38f;
    for (int j = 0; j < NCHUNK; j++) {
        g_pa[j * NCHAIN + chain] = A;
        g_pb[j * NCHAIN + chain] = B;
        g_pp[j * NCHAIN + chain] = P;
        float ca = g_sa[j * NCHAIN + chain];
        float cb = g_sb[j * NCHAIN + chain];
        float cp = g_sp[j * NCHAIN + chain];
        float np = P + Lw;
        float p  = fmaxf(np, cp);
        float e1 = __expf(np - p);
        float e2 = __expf(cp - p);
        A = e1 * A + e2 * ca;
        B = e1 * B + e2 * cb;
        P = p;
    }
}

__global__ __launch_bounds__(256) void wkv_pass3(const float* __restrict__ sd,
                                                 const float* __restrict__ sf)
{
    int g     = blockIdx.x * 256 + threadIdx.x;
    int chain = g & (NCHAIN - 1);
    int chunk = g >> 12;
    int b = chain >> 9;
    int d = chain & 511;
    int c = d & 255;
    bool second = d >= 256;

    float wdec = -__expf(sd[d] * (1.0f / (float)TT));
    float u    =  sf[d] * (1.0f / (float)TT);

    const size_t base = (size_t)b * TT * CC + c;
    float* xsp = g_xs + (size_t)b * TT * DD + d;

    float a  = g_pa[chunk * NCHAIN + chain];
    float bb = g_pb[chunk * NCHAIN + chain];
    float pp = g_pp[chunk * NCHAIN + chain];

    int tstart = chunk * CHLEN;
    for (int t0 = tstart; t0 < tstart + CHLEN; t0 += 8) {
        float kb[8], vb[8], sb[8];
        #pragma unroll
        for (int i = 0; i < 8; i++) {
            int t  = t0 + i;
            int ti = second ? (((t & 63) << 6) | (t >> 6)) : t;
            size_t off = base + (size_t)ti * CC;
            kb[i] = g_k[off];
            vb[i] = g_v[off];
            sb[i] = g_sr[base + (size_t)t * CC];
        }
        #pragma unroll
        for (int i = 0; i < 8; i++) {
            float kt = kb[i], vt = vb[i];
            float ww = u + kt;
            float d1 = pp - ww;
            float e  = __expf(-fabsf(d1));
            float e1 = (d1 >= 0.f) ? 1.f : e;
            float e2 = (d1 >= 0.f) ? e : 1.f;
            float out = __fdividef(e1 * a + e2 * vt, e1 * bb + e2);
            wkv_state(kt, vt, wdec, a, bb, pp);
            xsp[(size_t)(t0 + i) * DD] = rnd_tf32(out * sb[i]);
        }
    }
}

// ---------------- launch -----------------------------------------------------
extern "C" void kernel_launch(void* const* d_in, const int* in_sizes, int n_in,
                              void* d_out, int out_size)
{
    const float* x     = (const float*)d_in[0];
    const float* alpha = (const float*)d_in[1];
    const float* cw1   = (const float*)d_in[2];
    const float* cw3   = (const float*)d_in[3];
    const float* cw5   = (const float*)d_in[4];
    const float* Wk    = (const float*)d_in[5];
    const float* Wv    = (const float*)d_in[6];
    const float* Wr    = (const float*)d_in[7];
    const float* Wo    = (const float*)d_in[8];
    const float* sd    = (const float*)d_in[9];
    const float* sf    = (const float*)d_in[10];

    float *xf, *k, *v, *sr, *xs, *wk, *wv, *wr, *wo;
    cudaGetSymbolAddress((void**)&xf, g_xf);
    cudaGetSymbolAddress((void**)&k,  g_k);
    cudaGetSymbolAddress((void**)&v,  g_v);
    cudaGetSymbolAddress((void**)&sr, g_sr);
    cudaGetSymbolAddress((void**)&xs, g_xs);
    cudaGetSymbolAddress((void**)&wk, g_wk);
    cudaGetSymbolAddress((void**)&wv, g_wv);
    cudaGetSymbolAddress((void**)&wr, g_wr);
    cudaGetSymbolAddress((void**)&wo, g_wo);

    cudaFuncSetAttribute(gemm_qkv_kernel,
                         cudaFuncAttributeMaxDynamicSharedMemorySize, GS_BYTES);

    round_weights_kernel<<<(CC * DD + 255) / 256, 256>>>(Wk, Wv, Wr, Wo);
    combine_weights_kernel<<<1, 256>>>(alpha, cw1, cw3, cw5);
    omni_conv_kernel<<<BATCH * 32, 256>>>(x);

    // fused k / v / r(sigmoid) gemms: grid.x = 6 (3 groups x 2 n-blocks)
    dim3 g3(6, MM / 128);
    gemm_qkv_kernel<<<g3, 256, GS_BYTES>>>(xf, wk, wv, wr, k, v, sr, CC, 4);

    wkv_pass1<<<(NCHAIN * NCHUNK) / 256, 256>>>(sd);
    wkv_pass2<<<NCHAIN / 256, 256>>>(sd);
    wkv_pass3<<<(NCHAIN * NCHUNK) / 256, 256>>>(sd, sf);

    // output projection: grid.x = 2 (group 0 only), K = 512
    dim3 g1(2, MM / 128);
    gemm_qkv_kernel<<<g1, 256, GS_BYTES>>>(xs, wo, wo, wo,
                                           (float*)d_out, (float*)d_out,
                                           (float*)d_out, DD, 0);
}

// round 14
// speedup vs baseline: 1.8522x; 1.3187x over previous
#include <cuda_runtime.h>
#include <cuda_fp16.h>
#include <cstdint>

#define BATCH 8
#define HH    64
#define WW_   64
#define TT    4096
#define CC    256
#define DD    512
#define MM    (BATCH * TT)   // 32768

#define NCHAIN 4096
#define NCHUNK 32
#define CHLEN  128

// ---------------- scratch (static device globals; no runtime alloc) ----------
__device__ float  g_comb[25 * CC];
__device__ __half g_xfh[MM * CC];           // fp16 activations (GEMM A)
__device__ float  g_k [MM * CC];            // GEMM outputs stay fp32
__device__ float  g_v [MM * CC];
__device__ float  g_sr[MM * CC];
__device__ __half g_xsh[MM * DD];           // fp16 scan output (GEMM A)
__device__ float  g_sa[NCHUNK * NCHAIN];
__device__ float  g_sb[NCHUNK * NCHAIN];
__device__ float  g_sp[NCHUNK * NCHAIN];
__device__ float  g_pa[NCHUNK * NCHAIN];
__device__ float  g_pb[NCHUNK * NCHAIN];
__device__ float  g_pp[NCHUNK * NCHAIN];
// fp16 weights (K-major, W[n][k])
__device__ __half g_wkh[CC * CC];
__device__ __half g_wvh[CC * CC];
__device__ __half g_wrh[CC * CC];
__device__ __half g_woh[CC * DD];

// ---------------- 0) round weights to fp16 -----------------------------------
__global__ void round_weights_kernel(const float* __restrict__ Wk,
                                     const float* __restrict__ Wv,
                                     const float* __restrict__ Wr,
                                     const float* __restrict__ Wo)
{
    int i = blockIdx.x * 256 + threadIdx.x;
    if (i < CC * CC) {
        g_wkh[i] = __float2half_rn(Wk[i]);
        g_wvh[i] = __float2half_rn(Wv[i]);
        g_wrh[i] = __float2half_rn(Wr[i]);
    }
    if (i < CC * DD) g_woh[i] = __float2half_rn(Wo[i]);
}

// ---------------- 1) combine identity + 1x1 + 3x3 + 5x5 into one 5x5 ---------
__global__ void combine_weights_kernel(const float* __restrict__ alpha,
                                       const float* __restrict__ cw1,
                                       const float* __restrict__ cw3,
                                       const float* __restrict__ cw5)
{
    int c = threadIdx.x;
    float a0 = alpha[0], a1 = alpha[1], a2 = alpha[2], a3 = alpha[3];
    #pragma unroll
    for (int j = 0; j < 5; j++) {
        #pragma unroll
        for (int i = 0; i < 5; i++) {
            float v = a3 * cw5[c * 25 + j * 5 + i];
            if (j >= 1 && j <= 3 && i >= 1 && i <= 3)
                v += a2 * cw3[c * 9 + (j - 1) * 3 + (i - 1)];
            if (j == 2 && i == 2)
                v += a1 * cw1[c] + a0;
            g_comb[(j * 5 + i) * CC + c] = v;
        }
    }
}

// ---------------- 2) depthwise 5x5 conv, 2 output cols/block, fp16 out -------
__global__ __launch_bounds__(256) void omni_conv_kernel(const float* __restrict__ x)
{
    int b   = blockIdx.x >> 5;
    int xp  = blockIdx.x & 31;
    int xc0 = xp * 2;
    int c   = threadIdx.x;

    float wgt[25];
    #pragma unroll
    for (int j = 0; j < 25; j++) wgt[j] = g_comb[j * CC + c];

    const float* xin  = x     + (size_t)b * TT * CC + c;
    __half*      xout = g_xfh + (size_t)b * TT * CC + (size_t)xc0 * CC + c;

    float win[5][6];
    #pragma unroll
    for (int i = 0; i < 6; i++) { win[0][i] = 0.f; win[1][i] = 0.f; }
    #pragma unroll
    for (int r = 0; r < 3; r++) {
        #pragma unroll
        for (int i = 0; i < 6; i++) {
            int xx = xc0 - 2 + i;
            win[2 + r][i] = (xx >= 0 && xx < WW_) ? xin[((size_t)r * WW_ + xx) * CC] : 0.f;
        }
    }

    #pragma unroll 2
    for (int y = 0; y < HH; y++) {
        float acc0 = 0.f, acc1 = 0.f;
        #pragma unroll
        for (int j = 0; j < 5; j++)
            #pragma unroll
            for (int i = 0; i < 5; i++) {
                acc0 = fmaf(wgt[j * 5 + i], win[j][i],     acc0);
                acc1 = fmaf(wgt[j * 5 + i], win[j][i + 1], acc1);
            }
        xout[(size_t)y * WW_ * CC]      = __float2half_rn(acc0);
        xout[(size_t)y * WW_ * CC + CC] = __float2half_rn(acc1);

        #pragma unroll
        for (int j = 0; j < 4; j++)
            #pragma unroll
            for (int i = 0; i < 6; i++) win[j][i] = win[j + 1][i];
        int row = y + 3;
        #pragma unroll
        for (int i = 0; i < 6; i++) {
            int xx = xc0 - 2 + i;
            win[4][i] = (row < HH && xx >= 0 && xx < WW_)
                        ? xin[((size_t)row * WW_ + xx) * CC] : 0.f;
        }
    }
}

// ---------------- 3) fp16 mma.sync m16n8k16 GEMM -----------------------------
// fp16 significand (11 bits) == tf32 unit roundoff; data range tiny -> same
// accuracy as the tf32 path. 2x MAC per instruction, half the operand bytes.
// Block 128x128x32 (32 halves per k-tile = 16 u32), 8 warps (2x4), warp tile
// 64x32. smem row stride 20 u32: frag LDS.32 banks 20*qr+qc all-distinct;
// STS.128 staging (warp = 32 consecutive rows) covers all banks. 2 stages x
// (A+B) x 10240B = 40KB -> 2 CTAs/SM (register-capped anyway).
#define SH_   20
#define STW   (128 * SH_)                   // u32 per matrix per stage
#define GS_BYTES (4 * STW * 4)              // 40960

__global__ __launch_bounds__(256, 2) void gemm_qkv_kernel(
    const __half* __restrict__ A,
    const __half* __restrict__ W0, const __half* __restrict__ W1,
    const __half* __restrict__ W2,
    float* __restrict__ O0, float* __restrict__ O1, float* __restrict__ O2,
    int K, int actsel)
{
    extern __shared__ unsigned gsm[];
    const int tid = threadIdx.x;
    const int grp = blockIdx.x >> 1;               // 0..2 weight/output select
    const int bn  = (blockIdx.x & 1) * 128;
    const __half* W  = (grp == 0) ? W0 : (grp == 1) ? W1 : W2;
    float*       Out = (grp == 0) ? O0 : (grp == 1) ? O1 : O2;
    const int act = (actsel >> grp) & 1;
    const size_t bm = (size_t)blockIdx.y * 128;

    const int lane = tid & 31, wid = tid >> 5;
    const int wm = (wid & 1) * 64;
    const int wn = (wid >> 1) * 32;
    const int qr = lane >> 2;
    const int qc = lane & 3;

    // staging: thread -> row (tid&127), k-half (tid>>7); warp = 32 consec rows
    const int srow = tid & 127;
    const int sh   = tid >> 7;                      // 0/1 -> halves 0-15 / 16-31
    const __half* Ag = A + (bm + srow) * (size_t)K + sh * 16;
    const __half* Wg = W + (size_t)(bn + srow) * K + sh * 16;
    const int scol = sh * 8;                        // u32 col base in smem row

    const int NT = K >> 5;

    float acc[4][4][4];
    #pragma unroll
    for (int mf = 0; mf < 4; mf++)
        #pragma unroll
        for (int nf = 0; nf < 4; nf++)
            #pragma unroll
            for (int i = 0; i < 4; i++) acc[mf][nf][i] = 0.f;

    uint4 qa0, qa1, qw0, qw1;

    // prologue: load + stage ktile 0
    qa0 = *(const uint4*)(Ag);     qa1 = *(const uint4*)(Ag + 8);
    qw0 = *(const uint4*)(Wg);     qw1 = *(const uint4*)(Wg + 8);
    {
        unsigned* As = gsm;
        unsigned* Bs = gsm + STW;
        *(uint4*)&As[srow * SH_ + scol]     = qa0;
        *(uint4*)&As[srow * SH_ + scol + 4] = qa1;
        *(uint4*)&Bs[srow * SH_ + scol]     = qw0;
        *(uint4*)&Bs[srow * SH_ + scol + 4] = qw1;
    }
    __syncthreads();

    for (int kt = 0; kt < NT; kt++) {
        const bool more = (kt + 1 < NT);
        if (more) {
            const __half* a = Ag + (kt + 1) * 32;
            const __half* w = Wg + (kt + 1) * 32;
            qa0 = *(const uint4*)(a);  qa1 = *(const uint4*)(a + 8);
            qw0 = *(const uint4*)(w);  qw1 = *(const uint4*)(w + 8);
        }

        const unsigned* Asm = gsm + (kt & 1) * 2 * STW;
        const unsigned* Bsm = Asm + STW;

        #pragma unroll
        for (int s = 0; s < 2; s++) {             // two k16 steps per ktile
            const int cb = s * 8;
            unsigned b0[4], b1[4];
            #pragma unroll
            for (int nf = 0; nf < 4; nf++) {
                int n = wn + nf * 8 + qr;
                b0[nf] = Bsm[n * SH_ + cb + qc];
                b1[nf] = Bsm[n * SH_ + cb + qc + 4];
            }
            #pragma unroll
            for (int mf = 0; mf < 4; mf++) {
                int r0 = wm + mf * 16 + qr;
                unsigned a0 = Asm[r0 * SH_ + cb + qc];
                unsigned a1 = Asm[(r0 + 8) * SH_ + cb + qc];
                unsigned a2 = Asm[r0 * SH_ + cb + qc + 4];
                unsigned a3 = Asm[(r0 + 8) * SH_ + cb + qc + 4];
                #pragma unroll
                for (int nf = 0; nf < 4; nf++) {
                    asm volatile(
                        "mma.sync.aligned.m16n8k16.row.col.f32.f16.f16.f32 "
                        "{%0,%1,%2,%3}, {%4,%5,%6,%7}, {%8,%9}, {%0,%1,%2,%3};"
                        : "+f"(acc[mf][nf][0]), "+f"(acc[mf][nf][1]),
                          "+f"(acc[mf][nf][2]), "+f"(acc[mf][nf][3])
                        : "r"(a0), "r"(a1), "r"(a2), "r"(a3),
                          "r"(b0[nf]), "r"(b1[nf]));
                }
            }
        }

        if (more) {
            unsigned* AsN = gsm + ((kt + 1) & 1) * 2 * STW;
            unsigned* BsN = AsN + STW;
            *(uint4*)&AsN[srow * SH_ + scol]     = qa0;
            *(uint4*)&AsN[srow * SH_ + scol + 4] = qa1;
            *(uint4*)&BsN[srow * SH_ + scol]     = qw0;
            *(uint4*)&BsN[srow * SH_ + scol + 4] = qw1;
        }
        __syncthreads();
    }

    #pragma unroll
    for (int mf = 0; mf < 4; mf++) {
        size_t r0 = bm + wm + mf * 16 + qr;
        #pragma unroll
        for (int nf = 0; nf < 4; nf++) {
            int col = bn + wn + nf * 8 + qc * 2;
            float c0 = acc[mf][nf][0], c1 = acc[mf][nf][1];
            float c2 = acc[mf][nf][2], c3 = acc[mf][nf][3];
            if (act) {
                c0 = 1.0f / (1.0f + __expf(-c0));
                c1 = 1.0f / (1.0f + __expf(-c1));
                c2 = 1.0f / (1.0f + __expf(-c2));
                c3 = 1.0f / (1.0f + __expf(-c3));
            }
            *(float2*)(Out + r0 * 256 + col)       = make_float2(c0, c1);
            *(float2*)(Out + (r0 + 8) * 256 + col) = make_float2(c2, c3);
        }
    }
}

// ---------------- 4) WKV chunk-parallel scan ---------------------------------
__device__ __forceinline__ void wkv_state(float kt, float vt, float wdec,
                                          float& a, float& b, float& pp)
{
    float ww2 = pp + wdec;
    float d2  = ww2 - kt;
    float f   = __expf(-fabsf(d2));
    float f1  = (d2 >= 0.f) ? 1.f : f;
    float f2  = (d2 >= 0.f) ? f : 1.f;
    a  = f1 * a + f2 * vt;
    b  = f1 * b + f2;
    pp = fmaxf(ww2, kt);
}

__global__ __launch_bounds__(256) void wkv_pass1(const float* __restrict__ sd)
{
    int g     = blockIdx.x * 256 + threadIdx.x;
    int chain = g & (NCHAIN - 1);
    int chunk = g >> 12;
    int b = chain >> 9;
    int d = chain & 511;
    int c = d & 255;
    bool second = d >= 256;

    float wdec = -__expf(sd[d] * (1.0f / (float)TT));
    const size_t base = (size_t)b * TT * CC + c;

    float a = 0.f, bb = 0.f, pp = -1e38f;
    int tstart = chunk * CHLEN;

    for (int t0 = tstart; t0 < tstart + CHLEN; t0 += 8) {
        float kb[8], vb[8];
        #pragma unroll
        for (int i = 0; i < 8; i++) {
            int t  = t0 + i;
            int ti = second ? (((t & 63) << 6) | (t >> 6)) : t;
            size_t off = base + (size_t)ti * CC;
            kb[i] = g_k[off];
            vb[i] = g_v[off];
        }
        #pragma unroll
        for (int i = 0; i < 8; i++)
            wkv_state(kb[i], vb[i], wdec, a, bb, pp);
    }
    g_sa[chunk * NCHAIN + chain] = a;
    g_sb[chunk * NCHAIN + chain] = bb;
    g_sp[chunk * NCHAIN + chain] = pp;
}

__global__ __launch_bounds__(256) void wkv_pass2(const float* __restrict__ sd)
{
    int chain = blockIdx.x * 256 + threadIdx.x;
    int d = chain & 511;
    float wdec = -__expf(sd[d] * (1.0f / (float)TT));
    float Lw = (float)CHLEN * wdec;

    float A = 0.f, B = 0.f, P = -1e38f;
    for (int j = 0; j < NCHUNK; j++) {
        g_pa[j * NCHAIN + chain] = A;
        g_pb[j * NCHAIN + chain] = B;
        g_pp[j * NCHAIN + chain] = P;
        float ca = g_sa[j * NCHAIN + chain];
        float cb = g_sb[j * NCHAIN + chain];
        float cp = g_sp[j * NCHAIN + chain];
        float np = P + Lw;
        float p  = fmaxf(np, cp);
        float e1 = __expf(np - p);
        float e2 = __expf(cp - p);
        A = e1 * A + e2 * ca;
        B = e1 * B + e2 * cb;
        P = p;
    }
}

__global__ __launch_bounds__(256) void wkv_pass3(const float* __restrict__ sd,
                                                 const float* __restrict__ sf)
{
    int g     = blockIdx.x * 256 + threadIdx.x;
    int chain = g & (NCHAIN - 1);
    int chunk = g >> 12;
    int b = chain >> 9;
    int d = chain & 511;
    int c = d & 255;
    bool second = d >= 256;

    float wdec = -__expf(sd[d] * (1.0f / (float)TT));
    float u    =  sf[d] * (1.0f / (float)TT);

    const size_t base = (size_t)b * TT * CC + c;
    __half* xsp = g_xsh + (size_t)b * TT * DD + d;

    float a  = g_pa[chunk * NCHAIN + chain];
    float bb = g_pb[chunk * NCHAIN + chain];
    float pp = g_pp[chunk * NCHAIN + chain];

    int tstart = chunk * CHLEN;
    for (int t0 = tstart; t0 < tstart + CHLEN; t0 += 8) {
        float kb[8], vb[8], sb[8];
        #pragma unroll
        for (int i = 0; i < 8; i++) {
            int t  = t0 + i;
            int ti = second ? (((t & 63) << 6) | (t >> 6)) : t;
            size_t off = base + (size_t)ti * CC;
            kb[i] = g_k[off];
            vb[i] = g_v[off];
            sb[i] = g_sr[base + (size_t)t * CC];
        }
        #pragma unroll
        for (int i = 0; i < 8; i++) {
            float kt = kb[i], vt = vb[i];
            float ww = u + kt;
            float d1 = pp - ww;
            float e  = __expf(-fabsf(d1));
            float e1 = (d1 >= 0.f) ? 1.f : e;
            float e2 = (d1 >= 0.f) ? e : 1.f;
            float out = __fdividef(e1 * a + e2 * vt, e1 * bb + e2);
            wkv_state(kt, vt, wdec, a, bb, pp);
            xsp[(size_t)(t0 + i) * DD] = __float2half_rn(out * sb[i]);
        }
    }
}

// ---------------- launch -----------------------------------------------------
extern "C" void kernel_launch(void* const* d_in, const int* in_sizes, int n_in,
                              void* d_out, int out_size)
{
    const float* x     = (const float*)d_in[0];
    const float* alpha = (const float*)d_in[1];
    const float* cw1   = (const float*)d_in[2];
    const float* cw3   = (const float*)d_in[3];
    const float* cw5   = (const float*)d_in[4];
    const float* Wk    = (const float*)d_in[5];
    const float* Wv    = (const float*)d_in[6];
    const float* Wr    = (const float*)d_in[7];
    const float* Wo    = (const float*)d_in[8];
    const float* sd    = (const float*)d_in[9];
    const float* sf    = (const float*)d_in[10];

    float *k, *v, *sr;
    __half *xfh, *xsh, *wkh, *wvh, *wrh, *woh;
    cudaGetSymbolAddress((void**)&xfh, g_xfh);
    cudaGetSymbolAddress((void**)&k,   g_k);
    cudaGetSymbolAddress((void**)&v,   g_v);
    cudaGetSymbolAddress((void**)&sr,  g_sr);
    cudaGetSymbolAddress((void**)&xsh, g_xsh);
    cudaGetSymbolAddress((void**)&wkh, g_wkh);
    cudaGetSymbolAddress((void**)&wvh, g_wvh);
    cudaGetSymbolAddress((void**)&wrh, g_wrh);
    cudaGetSymbolAddress((void**)&woh, g_woh);

    cudaFuncSetAttribute(gemm_qkv_kernel,
                         cudaFuncAttributeMaxDynamicSharedMemorySize, GS_BYTES);

    round_weights_kernel<<<(CC * DD + 255) / 256, 256>>>(Wk, Wv, Wr, Wo);
    combine_weights_kernel<<<1, 256>>>(alpha, cw1, cw3, cw5);
    omni_conv_kernel<<<BATCH * 32, 256>>>(x);

    // fused k / v / r(sigmoid) gemms: grid.x = 6 (3 groups x 2 n-blocks)
    dim3 g3(6, MM / 128);
    gemm_qkv_kernel<<<g3, 256, GS_BYTES>>>(xfh, wkh, wvh, wrh, k, v, sr, CC, 4);

    wkv_pass1<<<(NCHAIN * NCHUNK) / 256, 256>>>(sd);
    wkv_pass2<<<NCHAIN / 256, 256>>>(sd);
    wkv_pass3<<<(NCHAIN * NCHUNK) / 256, 256>>>(sd, sf);

    // output projection: grid.x = 2 (group 0 only), K = 512
    dim3 g1(2, MM / 128);
    gemm_qkv_kernel<<<g1, 256, GS_BYTES>>>(xsh, woh, woh, woh,
                                           (float*)d_out, (float*)d_out,
                                           (float*)d_out, DD, 0);
}

// round 15
// speedup vs baseline: 1.9203x; 1.0368x over previous
#include <cuda_runtime.h>
#include <cuda_fp16.h>
#include <cstdint>

#define BATCH 8
#define HH    64
#define WW_   64
#define TT    4096
#define CC    256
#define DD    512
#define MM    (BATCH * TT)   // 32768

#define NCHAIN 4096
#define NCHUNK 32
#define CHLEN  128

// ---------------- scratch (static device globals; no runtime alloc) ----------
__device__ float  g_comb[25 * CC];
__device__ __half g_xfh[MM * CC];           // fp16 activations (GEMM A)
__device__ float  g_k [MM * CC];            // GEMM outputs stay fp32
__device__ float  g_v [MM * CC];
__device__ float  g_sr[MM * CC];
__device__ __half g_xsh[MM * DD];           // fp16 scan output (GEMM A)
__device__ float  g_sa[NCHUNK * NCHAIN];
__device__ float  g_sb[NCHUNK * NCHAIN];
__device__ float  g_sp[NCHUNK * NCHAIN];
__device__ float  g_pa[NCHUNK * NCHAIN];
__device__ float  g_pb[NCHUNK * NCHAIN];
__device__ float  g_pp[NCHUNK * NCHAIN];
// fp16 weights (K-major, W[n][k])
__device__ __half g_wkh[CC * CC];
__device__ __half g_wvh[CC * CC];
__device__ __half g_wrh[CC * CC];
__device__ __half g_woh[CC * DD];

// ---------------- 0) round weights to fp16 -----------------------------------
__global__ void round_weights_kernel(const float* __restrict__ Wk,
                                     const float* __restrict__ Wv,
                                     const float* __restrict__ Wr,
                                     const float* __restrict__ Wo)
{
    int i = blockIdx.x * 256 + threadIdx.x;
    if (i < CC * CC) {
        g_wkh[i] = __float2half_rn(Wk[i]);
        g_wvh[i] = __float2half_rn(Wv[i]);
        g_wrh[i] = __float2half_rn(Wr[i]);
    }
    if (i < CC * DD) g_woh[i] = __float2half_rn(Wo[i]);
}

// ---------------- 1) combine identity + 1x1 + 3x3 + 5x5 into one 5x5 ---------
__global__ void combine_weights_kernel(const float* __restrict__ alpha,
                                       const float* __restrict__ cw1,
                                       const float* __restrict__ cw3,
                                       const float* __restrict__ cw5)
{
    int c = threadIdx.x;
    float a0 = alpha[0], a1 = alpha[1], a2 = alpha[2], a3 = alpha[3];
    #pragma unroll
    for (int j = 0; j < 5; j++) {
        #pragma unroll
        for (int i = 0; i < 5; i++) {
            float v = a3 * cw5[c * 25 + j * 5 + i];
            if (j >= 1 && j <= 3 && i >= 1 && i <= 3)
                v += a2 * cw3[c * 9 + (j - 1) * 3 + (i - 1)];
            if (j == 2 && i == 2)
                v += a1 * cw1[c] + a0;
            g_comb[(j * 5 + i) * CC + c] = v;
        }
    }
}

// ---------------- 2) depthwise 5x5 conv, 2 output cols/block, fp16 out -------
__global__ __launch_bounds__(256) void omni_conv_kernel(const float* __restrict__ x)
{
    int b   = blockIdx.x >> 5;
    int xp  = blockIdx.x & 31;
    int xc0 = xp * 2;
    int c   = threadIdx.x;

    float wgt[25];
    #pragma unroll
    for (int j = 0; j < 25; j++) wgt[j] = g_comb[j * CC + c];

    const float* xin  = x     + (size_t)b * TT * CC + c;
    __half*      xout = g_xfh + (size_t)b * TT * CC + (size_t)xc0 * CC + c;

    float win[5][6];
    #pragma unroll
    for (int i = 0; i < 6; i++) { win[0][i] = 0.f; win[1][i] = 0.f; }
    #pragma unroll
    for (int r = 0; r < 3; r++) {
        #pragma unroll
        for (int i = 0; i < 6; i++) {
            int xx = xc0 - 2 + i;
            win[2 + r][i] = (xx >= 0 && xx < WW_) ? xin[((size_t)r * WW_ + xx) * CC] : 0.f;
        }
    }

    #pragma unroll 2
    for (int y = 0; y < HH; y++) {
        float acc0 = 0.f, acc1 = 0.f;
        #pragma unroll
        for (int j = 0; j < 5; j++)
            #pragma unroll
            for (int i = 0; i < 5; i++) {
                acc0 = fmaf(wgt[j * 5 + i], win[j][i],     acc0);
                acc1 = fmaf(wgt[j * 5 + i], win[j][i + 1], acc1);
            }
        xout[(size_t)y * WW_ * CC]      = __float2half_rn(acc0);
        xout[(size_t)y * WW_ * CC + CC] = __float2half_rn(acc1);

        #pragma unroll
        for (int j = 0; j < 4; j++)
            #pragma unroll
            for (int i = 0; i < 6; i++) win[j][i] = win[j + 1][i];
        int row = y + 3;
        #pragma unroll
        for (int i = 0; i < 6; i++) {
            int xx = xc0 - 2 + i;
            win[4][i] = (row < HH && xx >= 0 && xx < WW_)
                        ? xin[((size_t)row * WW_ + xx) * CC] : 0.f;
        }
    }
}

// ---------------- 3) fp16 mma.sync m16n8k16 GEMM + ldmatrix frags ------------
// Same math/order as R14 (bit-identical); fragment loads via LDSM.x4:
// per warp-ktile 12 LDSM.x4 replace 48 LDS.32. Stride-20 rows: each LDSM
// 8-address phase covers banks {20r mod 32}+0..3 = all 32, conflict-free.
#define SH_   20
#define STW   (128 * SH_)                   // u32 per matrix per stage
#define GS_BYTES (4 * STW * 4)              // 40960

__device__ __forceinline__ void ldsm4(unsigned& r0, unsigned& r1,
                                      unsigned& r2, unsigned& r3, unsigned addr)
{
    asm volatile("ldmatrix.sync.aligned.m8n8.x4.shared.b16 {%0,%1,%2,%3}, [%4];"
                 : "=r"(r0), "=r"(r1), "=r"(r2), "=r"(r3) : "r"(addr));
}

__global__ __launch_bounds__(256, 2) void gemm_qkv_kernel(
    const __half* __restrict__ A,
    const __half* __restrict__ W0, const __half* __restrict__ W1,
    const __half* __restrict__ W2,
    float* __restrict__ O0, float* __restrict__ O1, float* __restrict__ O2,
    int K, int actsel)
{
    extern __shared__ unsigned gsm[];
    const unsigned smemB = (unsigned)__cvta_generic_to_shared(gsm);
    const int tid = threadIdx.x;
    const int grp = blockIdx.x >> 1;               // 0..2 weight/output select
    const int bn  = (blockIdx.x & 1) * 128;
    const __half* W  = (grp == 0) ? W0 : (grp == 1) ? W1 : W2;
    float*       Out = (grp == 0) ? O0 : (grp == 1) ? O1 : O2;
    const int act = (actsel >> grp) & 1;
    const size_t bm = (size_t)blockIdx.y * 128;

    const int lane = tid & 31, wid = tid >> 5;
    const int wm = (wid & 1) * 64;
    const int wn = (wid >> 1) * 32;
    const int qr = lane >> 2;
    const int qc = lane & 3;

    // ldmatrix lane->address components (byte offsets within a stage matrix)
    // A x4: matrices (m0-7,k0-7),(m8-15,k0-7),(m0-7,k8-15),(m8-15,k8-15)
    //   lane: row = wm + (lane&15), chunk = lane>>4
    const unsigned aLane = (unsigned)(((wm + (lane & 15)) * SH_ + (lane >> 4) * 4) * 4);
    // B x4 for nf pair j: matrices (nf=2j,c0),(nf=2j,c1),(nf=2j+1,c0),(nf=2j+1,c1)
    //   lane: row = wn + (lane&7) + ((lane>>4)+2j)*8, chunk = (lane>>3)&1
    const unsigned bLane = (unsigned)(((wn + (lane & 7) + (lane >> 4) * 8) * SH_
                                       + ((lane >> 3) & 1) * 4) * 4);

    // staging: thread -> row (tid&127), k-half (tid>>7); warp = 32 consec rows
    const int srow = tid & 127;
    const int sh   = tid >> 7;
    const __half* Ag = A + (bm + srow) * (size_t)K + sh * 16;
    const __half* Wg = W + (size_t)(bn + srow) * K + sh * 16;
    const int scol = sh * 8;

    const int NT = K >> 5;

    float acc[4][4][4];
    #pragma unroll
    for (int mf = 0; mf < 4; mf++)
        #pragma unroll
        for (int nf = 0; nf < 4; nf++)
            #pragma unroll
            for (int i = 0; i < 4; i++) acc[mf][nf][i] = 0.f;

    uint4 qa0, qa1, qw0, qw1;

    // prologue: load + stage ktile 0
    qa0 = *(const uint4*)(Ag);     qa1 = *(const uint4*)(Ag + 8);
    qw0 = *(const uint4*)(Wg);     qw1 = *(const uint4*)(Wg + 8);
    {
        unsigned* As = gsm;
        unsigned* Bs = gsm + STW;
        *(uint4*)&As[srow * SH_ + scol]     = qa0;
        *(uint4*)&As[srow * SH_ + scol + 4] = qa1;
        *(uint4*)&Bs[srow * SH_ + scol]     = qw0;
        *(uint4*)&Bs[srow * SH_ + scol + 4] = qw1;
    }
    __syncthreads();

    for (int kt = 0; kt < NT; kt++) {
        const bool more = (kt + 1 < NT);
        if (more) {
            const __half* a = Ag + (kt + 1) * 32;
            const __half* w = Wg + (kt + 1) * 32;
            qa0 = *(const uint4*)(a);  qa1 = *(const uint4*)(a + 8);
            qw0 = *(const uint4*)(w);  qw1 = *(const uint4*)(w + 8);
        }

        const unsigned stA = smemB + (unsigned)((kt & 1) * 2 * STW) * 4u;
        const unsigned stB = stA + (unsigned)STW * 4u;

        #pragma unroll
        for (int s = 0; s < 2; s++) {             // two k16 steps per ktile
            const unsigned so = (unsigned)(s * 8) * 4u;   // byte offset of k16 chunk
            unsigned b0[4], b1[4];
            ldsm4(b0[0], b1[0], b0[1], b1[1], stB + bLane + so);
            ldsm4(b0[2], b1[2], b0[3], b1[3], stB + bLane + so + (unsigned)(16 * SH_ * 4));
            #pragma unroll
            for (int mf = 0; mf < 4; mf++) {
                unsigned a0, a1, a2, a3;
                ldsm4(a0, a1, a2, a3,
                      stA + aLane + so + (unsigned)(mf * 16 * SH_ * 4));
                #pragma unroll
                for (int nf = 0; nf < 4; nf++) {
                    asm volatile(
                        "mma.sync.aligned.m16n8k16.row.col.f32.f16.f16.f32 "
                        "{%0,%1,%2,%3}, {%4,%5,%6,%7}, {%8,%9}, {%0,%1,%2,%3};"
                        : "+f"(acc[mf][nf][0]), "+f"(acc[mf][nf][1]),
                          "+f"(acc[mf][nf][2]), "+f"(acc[mf][nf][3])
                        : "r"(a0), "r"(a1), "r"(a2), "r"(a3),
                          "r"(b0[nf]), "r"(b1[nf]));
                }
            }
        }

        if (more) {
            unsigned* AsN = gsm + ((kt + 1) & 1) * 2 * STW;
            unsigned* BsN = AsN + STW;
            *(uint4*)&AsN[srow * SH_ + scol]     = qa0;
            *(uint4*)&AsN[srow * SH_ + scol + 4] = qa1;
            *(uint4*)&BsN[srow * SH_ + scol]     = qw0;
            *(uint4*)&BsN[srow * SH_ + scol + 4] = qw1;
        }
        __syncthreads();
    }

    #pragma unroll
    for (int mf = 0; mf < 4; mf++) {
        size_t r0 = bm + wm + mf * 16 + qr;
        #pragma unroll
        for (int nf = 0; nf < 4; nf++) {
            int col = bn + wn + nf * 8 + qc * 2;
            float c0 = acc[mf][nf][0], c1 = acc[mf][nf][1];
            float c2 = acc[mf][nf][2], c3 = acc[mf][nf][3];
            if (act) {
                c0 = 1.0f / (1.0f + __expf(-c0));
                c1 = 1.0f / (1.0f + __expf(-c1));
                c2 = 1.0f / (1.0f + __expf(-c2));
                c3 = 1.0f / (1.0f + __expf(-c3));
            }
            *(float2*)(Out + r0 * 256 + col)       = make_float2(c0, c1);
            *(float2*)(Out + (r0 + 8) * 256 + col) = make_float2(c2, c3);
        }
    }
}

// ---------------- 4) WKV chunk-parallel scan ---------------------------------
__device__ __forceinline__ void wkv_state(float kt, float vt, float wdec,
                                          float& a, float& b, float& pp)
{
    float ww2 = pp + wdec;
    float d2  = ww2 - kt;
    float f   = __expf(-fabsf(d2));
    float f1  = (d2 >= 0.f) ? 1.f : f;
    float f2  = (d2 >= 0.f) ? f : 1.f;
    a  = f1 * a + f2 * vt;
    b  = f1 * b + f2;
    pp = fmaxf(ww2, kt);
}

__global__ __launch_bounds__(256) void wkv_pass1(const float* __restrict__ sd)
{
    int g     = blockIdx.x * 256 + threadIdx.x;
    int chain = g & (NCHAIN - 1);
    int chunk = g >> 12;
    int b = chain >> 9;
    int d = chain & 511;
    int c = d & 255;
    bool second = d >= 256;

    float wdec = -__expf(sd[d] * (1.0f / (float)TT));
    const size_t base = (size_t)b * TT * CC + c;

    float a = 0.f, bb = 0.f, pp = -1e38f;
    int tstart = chunk * CHLEN;

    for (int t0 = tstart; t0 < tstart + CHLEN; t0 += 8) {
        float kb[8], vb[8];
        #pragma unroll
        for (int i = 0; i < 8; i++) {
            int t  = t0 + i;
            int ti = second ? (((t & 63) << 6) | (t >> 6)) : t;
            size_t off = base + (size_t)ti * CC;
            kb[i] = g_k[off];
            vb[i] = g_v[off];
        }
        #pragma unroll
        for (int i = 0; i < 8; i++)
            wkv_state(kb[i], vb[i], wdec, a, bb, pp);
    }
    g_sa[chunk * NCHAIN + chain] = a;
    g_sb[chunk * NCHAIN + chain] = bb;
    g_sp[chunk * NCHAIN + chain] = pp;
}

__global__ __launch_bounds__(256) void wkv_pass2(const float* __restrict__ sd)
{
    int chain = blockIdx.x * 256 + threadIdx.x;
    int d = chain & 511;
    float wdec = -__expf(sd[d] * (1.0f / (float)TT));
    float Lw = (float)CHLEN * wdec;

    float A = 0.f, B = 0.f, P = -1e38f;
    for (int j = 0; j < NCHUNK; j++) {
        g_pa[j * NCHAIN + chain] = A;
        g_pb[j * NCHAIN + chain] = B;
        g_pp[j * NCHAIN + chain] = P;
        float ca = g_sa[j * NCHAIN + chain];
        float cb = g_sb[j * NCHAIN + chain];
        float cp = g_sp[j * NCHAIN + chain];
        float np = P + Lw;
        float p  = fmaxf(np, cp);
        float e1 = __expf(np - p);
        float e2 = __expf(cp - p);
        A = e1 * A + e2 * ca;
        B = e1 * B + e2 * cb;
        P = p;
    }
}

__global__ __launch_bounds__(256) void wkv_pass3(const float* __restrict__ sd,
                                                 const float* __restrict__ sf)
{
    int g     = blockIdx.x * 256 + threadIdx.x;
    int chain = g & (NCHAIN - 1);
    int chunk = g >> 12;
    int b = chain >> 9;
    int d = chain & 511;
    int c = d & 255;
    bool second = d >= 256;

    float wdec = -__expf(sd[d] * (1.0f / (float)TT));
    float u    =  sf[d] * (1.0f / (float)TT);

    const size_t base = (size_t)b * TT * CC + c;
    __half* xsp = g_xsh + (size_t)b * TT * DD + d;

    float a  = g_pa[chunk * NCHAIN + chain];
    float bb = g_pb[chunk * NCHAIN + chain];
    float pp = g_pp[chunk * NCHAIN + chain];

    int tstart = chunk * CHLEN;
    for (int t0 = tstart; t0 < tstart + CHLEN; t0 += 8) {
        float kb[8], vb[8], sb[8];
        #pragma unroll
        for (int i = 0; i < 8; i++) {
            int t  = t0 + i;
            int ti = second ? (((t & 63) << 6) | (t >> 6)) : t;
            size_t off = base + (size_t)ti * CC;
            kb[i] = g_k[off];
            vb[i] = g_v[off];
            sb[i] = g_sr[base + (size_t)t * CC];
        }
        #pragma unroll
        for (int i = 0; i < 8; i++) {
            float kt = kb[i], vt = vb[i];
            float ww = u + kt;
            float d1 = pp - ww;
            float e  = __expf(-fabsf(d1));
            float e1 = (d1 >= 0.f) ? 1.f : e;
            float e2 = (d1 >= 0.f) ? e : 1.f;
            float out = __fdividef(e1 * a + e2 * vt, e1 * bb + e2);
            wkv_state(kt, vt, wdec, a, bb, pp);
            xsp[(size_t)(t0 + i) * DD] = __float2half_rn(out * sb[i]);
        }
    }
}

// ---------------- launch -----------------------------------------------------
extern "C" void kernel_launch(void* const* d_in, const int* in_sizes, int n_in,
                              void* d_out, int out_size)
{
    const float* x     = (const float*)d_in[0];
    const float* alpha = (const float*)d_in[1];
    const float* cw1   = (const float*)d_in[2];
    const float* cw3   = (const float*)d_in[3];
    const float* cw5   = (const float*)d_in[4];
    const float* Wk    = (const float*)d_in[5];
    const float* Wv    = (const float*)d_in[6];
    const float* Wr    = (const float*)d_in[7];
    const float* Wo    = (const float*)d_in[8];
    const float* sd    = (const float*)d_in[9];
    const float* sf    = (const float*)d_in[10];

    float *k, *v, *sr;
    __half *xfh, *xsh, *wkh, *wvh, *wrh, *woh;
    cudaGetSymbolAddress((void**)&xfh, g_xfh);
    cudaGetSymbolAddress((void**)&k,   g_k);
    cudaGetSymbolAddress((void**)&v,   g_v);
    cudaGetSymbolAddress((void**)&sr,  g_sr);
    cudaGetSymbolAddress((void**)&xsh, g_xsh);
    cudaGetSymbolAddress((void**)&wkh, g_wkh);
    cudaGetSymbolAddress((void**)&wvh, g_wvh);
    cudaGetSymbolAddress((void**)&wrh, g_wrh);
    cudaGetSymbolAddress((void**)&woh, g_woh);

    cudaFuncSetAttribute(gemm_qkv_kernel,
                         cudaFuncAttributeMaxDynamicSharedMemorySize, GS_BYTES);

    round_weights_kernel<<<(CC * DD + 255) / 256, 256>>>(Wk, Wv, Wr, Wo);
    combine_weights_kernel<<<1, 256>>>(alpha, cw1, cw3, cw5);
    omni_conv_kernel<<<BATCH * 32, 256>>>(x);

    // fused k / v / r(sigmoid) gemms: grid.x = 6 (3 groups x 2 n-blocks)
    dim3 g3(6, MM / 128);
    gemm_qkv_kernel<<<g3, 256, GS_BYTES>>>(xfh, wkh, wvh, wrh, k, v, sr, CC, 4);

    wkv_pass1<<<(NCHAIN * NCHUNK) / 256, 256>>>(sd);
    wkv_pass2<<<NCHAIN / 256, 256>>>(sd);
    wkv_pass3<<<(NCHAIN * NCHUNK) / 256, 256>>>(sd, sf);

    // output projection: grid.x = 2 (group 0 only), K = 512
    dim3 g1(2, MM / 128);
    gemm_qkv_kernel<<<g1, 256, GS_BYTES>>>(xsh, woh, woh, woh,
                                           (float*)d_out, (float*)d_out,
                                           (float*)d_out, DD, 0);
}

// round 16
// speedup vs baseline: 2.0188x; 1.0513x over previous
#include <cuda_runtime.h>
#include <cuda_fp16.h>
#include <cstdint>

#define BATCH 8
#define HH    64
#define WW_   64
#define TT    4096
#define CC    256
#define DD    512
#define MM    (BATCH * TT)   // 32768

#define NCHAIN 4096
#define NCHUNK 32
#define CHLEN  128

// ---------------- scratch (static device globals; no runtime alloc) ----------
__device__ float  g_comb[25 * CC];
__device__ __half g_xfh[MM * CC];           // fp16 activations (GEMM A)
__device__ float  g_k [MM * CC];            // GEMM outputs stay fp32
__device__ float  g_v [MM * CC];
__device__ float  g_sr[MM * CC];
__device__ __half g_xsh[MM * DD];           // fp16 scan output (GEMM A)
__device__ float  g_sa[NCHUNK * NCHAIN];
__device__ float  g_sb[NCHUNK * NCHAIN];
__device__ float  g_sp[NCHUNK * NCHAIN];
__device__ float  g_pa[NCHUNK * NCHAIN];
__device__ float  g_pb[NCHUNK * NCHAIN];
__device__ float  g_pp[NCHUNK * NCHAIN];
// fp16 weights (K-major, W[n][k])
__device__ __half g_wkh[CC * CC];
__device__ __half g_wvh[CC * CC];
__device__ __half g_wrh[CC * CC];
__device__ __half g_woh[CC * DD];

__device__ __forceinline__ void cp16(unsigned dst, const void* src) {
    asm volatile("cp.async.ca.shared.global [%0], [%1], 16;" :: "r"(dst), "l"(src));
}
#define CP_COMMIT() asm volatile("cp.async.commit_group;" ::: "memory")
#define CP_WAIT1()  asm volatile("cp.async.wait_group 1;"  ::: "memory")

// ---------------- 0) round weights to fp16 -----------------------------------
__global__ void round_weights_kernel(const float* __restrict__ Wk,
                                     const float* __restrict__ Wv,
                                     const float* __restrict__ Wr,
                                     const float* __restrict__ Wo)
{
    int i = blockIdx.x * 256 + threadIdx.x;
    if (i < CC * CC) {
        g_wkh[i] = __float2half_rn(Wk[i]);
        g_wvh[i] = __float2half_rn(Wv[i]);
        g_wrh[i] = __float2half_rn(Wr[i]);
    }
    if (i < CC * DD) g_woh[i] = __float2half_rn(Wo[i]);
}

// ---------------- 1) combine identity + 1x1 + 3x3 + 5x5 into one 5x5 ---------
__global__ void combine_weights_kernel(const float* __restrict__ alpha,
                                       const float* __restrict__ cw1,
                                       const float* __restrict__ cw3,
                                       const float* __restrict__ cw5)
{
    int c = threadIdx.x;
    float a0 = alpha[0], a1 = alpha[1], a2 = alpha[2], a3 = alpha[3];
    #pragma unroll
    for (int j = 0; j < 5; j++) {
        #pragma unroll
        for (int i = 0; i < 5; i++) {
            float v = a3 * cw5[c * 25 + j * 5 + i];
            if (j >= 1 && j <= 3 && i >= 1 && i <= 3)
                v += a2 * cw3[c * 9 + (j - 1) * 3 + (i - 1)];
            if (j == 2 && i == 2)
                v += a1 * cw1[c] + a0;
            g_comb[(j * 5 + i) * CC + c] = v;
        }
    }
}

// ---------------- 2) depthwise 5x5 conv, 2 output cols/block, fp16 out -------
__global__ __launch_bounds__(256) void omni_conv_kernel(const float* __restrict__ x)
{
    int b   = blockIdx.x >> 5;
    int xp  = blockIdx.x & 31;
    int xc0 = xp * 2;
    int c   = threadIdx.x;

    float wgt[25];
    #pragma unroll
    for (int j = 0; j < 25; j++) wgt[j] = g_comb[j * CC + c];

    const float* xin  = x     + (size_t)b * TT * CC + c;
    __half*      xout = g_xfh + (size_t)b * TT * CC + (size_t)xc0 * CC + c;

    float win[5][6];
    #pragma unroll
    for (int i = 0; i < 6; i++) { win[0][i] = 0.f; win[1][i] = 0.f; }
    #pragma unroll
    for (int r = 0; r < 3; r++) {
        #pragma unroll
        for (int i = 0; i < 6; i++) {
            int xx = xc0 - 2 + i;
            win[2 + r][i] = (xx >= 0 && xx < WW_) ? xin[((size_t)r * WW_ + xx) * CC] : 0.f;
        }
    }

    #pragma unroll 2
    for (int y = 0; y < HH; y++) {
        float acc0 = 0.f, acc1 = 0.f;
        #pragma unroll
        for (int j = 0; j < 5; j++)
            #pragma unroll
            for (int i = 0; i < 5; i++) {
                acc0 = fmaf(wgt[j * 5 + i], win[j][i],     acc0);
                acc1 = fmaf(wgt[j * 5 + i], win[j][i + 1], acc1);
            }
        xout[(size_t)y * WW_ * CC]      = __float2half_rn(acc0);
        xout[(size_t)y * WW_ * CC + CC] = __float2half_rn(acc1);

        #pragma unroll
        for (int j = 0; j < 4; j++)
            #pragma unroll
            for (int i = 0; i < 6; i++) win[j][i] = win[j + 1][i];
        int row = y + 3;
        #pragma unroll
        for (int i = 0; i < 6; i++) {
            int xx = xc0 - 2 + i;
            win[4][i] = (row < HH && xx >= 0 && xx < WW_)
                        ? xin[((size_t)row * WW_ + xx) * CC] : 0.f;
        }
    }
}

// ---------------- 3) fp16 m16n8k16 GEMM + ldmatrix + cp.async 3-stage --------
// Bit-identical math to R15; cp.async moves global->smem transfers 2 stages
// ahead of compute, so the per-iteration chain is just barrier + LDSM + HMMA.
#define SH_   20
#define STW   (128 * SH_)                   // u32 per matrix per stage
#define GS_BYTES (6 * STW * 4)              // 3 stages x (A+B) = 61440

__device__ __forceinline__ void ldsm4(unsigned& r0, unsigned& r1,
                                      unsigned& r2, unsigned& r3, unsigned addr)
{
    asm volatile("ldmatrix.sync.aligned.m8n8.x4.shared.b16 {%0,%1,%2,%3}, [%4];"
                 : "=r"(r0), "=r"(r1), "=r"(r2), "=r"(r3) : "r"(addr));
}

__global__ __launch_bounds__(256, 2) void gemm_qkv_kernel(
    const __half* __restrict__ A,
    const __half* __restrict__ W0, const __half* __restrict__ W1,
    const __half* __restrict__ W2,
    float* __restrict__ O0, float* __restrict__ O1, float* __restrict__ O2,
    int K, int actsel)
{
    extern __shared__ unsigned gsm[];
    const unsigned smemB = (unsigned)__cvta_generic_to_shared(gsm);
    const int tid = threadIdx.x;
    const int grp = blockIdx.x >> 1;               // 0..2 weight/output select
    const int bn  = (blockIdx.x & 1) * 128;
    const __half* W  = (grp == 0) ? W0 : (grp == 1) ? W1 : W2;
    float*       Out = (grp == 0) ? O0 : (grp == 1) ? O1 : O2;
    const int act = (actsel >> grp) & 1;
    const size_t bm = (size_t)blockIdx.y * 128;

    const int lane = tid & 31, wid = tid >> 5;
    const int wm = (wid & 1) * 64;
    const int wn = (wid >> 1) * 32;
    const int qr = lane >> 2;
    const int qc = lane & 3;

    // ldmatrix lane->address components (byte offsets within a stage matrix)
    const unsigned aLane = (unsigned)(((wm + (lane & 15)) * SH_ + (lane >> 4) * 4) * 4);
    const unsigned bLane = (unsigned)(((wn + (lane & 7) + (lane >> 4) * 8) * SH_
                                       + ((lane >> 3) & 1) * 4) * 4);

    // cp.async staging: thread -> row (tid&127), k-half (tid>>7)
    const int srow = tid & 127;
    const int sh   = tid >> 7;
    const __half* Ag = A + (bm + srow) * (size_t)K + sh * 16;
    const __half* Wg = W + (size_t)(bn + srow) * K + sh * 16;
    const unsigned dRow = smemB + (unsigned)((srow * SH_ + sh * 8) * 4);

    const int NT = K >> 5;

    float acc[4][4][4];
    #pragma unroll
    for (int mf = 0; mf < 4; mf++)
        #pragma unroll
        for (int nf = 0; nf < 4; nf++)
            #pragma unroll
            for (int i = 0; i < 4; i++) acc[mf][nf][i] = 0.f;

    // prologue: stages 0 and 1 in flight
    #pragma unroll
    for (int s = 0; s < 2; s++) {
        const unsigned off = (unsigned)(s * 2 * STW) * 4u;
        const __half* a = Ag + s * 32;
        const __half* w = Wg + s * 32;
        cp16(dRow + off,      a);
        cp16(dRow + off + 16, a + 8);
        cp16(dRow + off + (unsigned)STW * 4u,      w);
        cp16(dRow + off + (unsigned)STW * 4u + 16, w + 8);
        CP_COMMIT();
    }

    for (int kt = 0; kt < NT; kt++) {
        CP_WAIT1();
        __syncthreads();

        if (kt + 2 < NT) {
            const int st = (kt + 2) % 3;
            const unsigned off = (unsigned)(st * 2 * STW) * 4u;
            const __half* a = Ag + (kt + 2) * 32;
            const __half* w = Wg + (kt + 2) * 32;
            cp16(dRow + off,      a);
            cp16(dRow + off + 16, a + 8);
            cp16(dRow + off + (unsigned)STW * 4u,      w);
            cp16(dRow + off + (unsigned)STW * 4u + 16, w + 8);
        }
        CP_COMMIT();

        const unsigned stA = smemB + (unsigned)((kt % 3) * 2 * STW) * 4u;
        const unsigned stB = stA + (unsigned)STW * 4u;

        #pragma unroll
        for (int s = 0; s < 2; s++) {             // two k16 steps per ktile
            const unsigned so = (unsigned)(s * 8) * 4u;
            unsigned b0[4], b1[4];
            ldsm4(b0[0], b1[0], b0[1], b1[1], stB + bLane + so);
            ldsm4(b0[2], b1[2], b0[3], b1[3], stB + bLane + so + (unsigned)(16 * SH_ * 4));
            #pragma unroll
            for (int mf = 0; mf < 4; mf++) {
                unsigned a0, a1, a2, a3;
                ldsm4(a0, a1, a2, a3,
                      stA + aLane + so + (unsigned)(mf * 16 * SH_ * 4));
                #pragma unroll
                for (int nf = 0; nf < 4; nf++) {
                    asm volatile(
                        "mma.sync.aligned.m16n8k16.row.col.f32.f16.f16.f32 "
                        "{%0,%1,%2,%3}, {%4,%5,%6,%7}, {%8,%9}, {%0,%1,%2,%3};"
                        : "+f"(acc[mf][nf][0]), "+f"(acc[mf][nf][1]),
                          "+f"(acc[mf][nf][2]), "+f"(acc[mf][nf][3])
                        : "r"(a0), "r"(a1), "r"(a2), "r"(a3),
                          "r"(b0[nf]), "r"(b1[nf]));
                }
            }
        }
    }

    #pragma unroll
    for (int mf = 0; mf < 4; mf++) {
        size_t r0 = bm + wm + mf * 16 + qr;
        #pragma unroll
        for (int nf = 0; nf < 4; nf++) {
            int col = bn + wn + nf * 8 + qc * 2;
            float c0 = acc[mf][nf][0], c1 = acc[mf][nf][1];
            float c2 = acc[mf][nf][2], c3 = acc[mf][nf][3];
            if (act) {
                c0 = 1.0f / (1.0f + __expf(-c0));
                c1 = 1.0f / (1.0f + __expf(-c1));
                c2 = 1.0f / (1.0f + __expf(-c2));
                c3 = 1.0f / (1.0f + __expf(-c3));
            }
            *(float2*)(Out + r0 * 256 + col)       = make_float2(c0, c1);
            *(float2*)(Out + (r0 + 8) * 256 + col) = make_float2(c2, c3);
        }
    }
}

// ---------------- 4) WKV chunk-parallel scan ---------------------------------
__device__ __forceinline__ void wkv_state(float kt, float vt, float wdec,
                                          float& a, float& b, float& pp)
{
    float ww2 = pp + wdec;
    float d2  = ww2 - kt;
    float f   = __expf(-fabsf(d2));
    float f1  = (d2 >= 0.f) ? 1.f : f;
    float f2  = (d2 >= 0.f) ? f : 1.f;
    a  = f1 * a + f2 * vt;
    b  = f1 * b + f2;
    pp = fmaxf(ww2, kt);
}

__global__ __launch_bounds__(256) void wkv_pass1(const float* __restrict__ sd)
{
    int g     = blockIdx.x * 256 + threadIdx.x;
    int chain = g & (NCHAIN - 1);
    int chunk = g >> 12;
    int b = chain >> 9;
    int d = chain & 511;
    int c = d & 255;
    bool second = d >= 256;

    float wdec = -__expf(sd[d] * (1.0f / (float)TT));
    const size_t base = (size_t)b * TT * CC + c;

    float a = 0.f, bb = 0.f, pp = -1e38f;
    int tstart = chunk * CHLEN;

    for (int t0 = tstart; t0 < tstart + CHLEN; t0 += 8) {
        float kb[8], vb[8];
        #pragma unroll
        for (int i = 0; i < 8; i++) {
            int t  = t0 + i;
            int ti = second ? (((t & 63) << 6) | (t >> 6)) : t;
            size_t off = base + (size_t)ti * CC;
            kb[i] = g_k[off];
            vb[i] = g_v[off];
        }
        #pragma unroll
        for (int i = 0; i < 8; i++)
            wkv_state(kb[i], vb[i], wdec, a, bb, pp);
    }
    g_sa[chunk * NCHAIN + chain] = a;
    g_sb[chunk * NCHAIN + chain] = bb;
    g_sp[chunk * NCHAIN + chain] = pp;
}

__global__ __launch_bounds__(256) void wkv_pass2(const float* __restrict__ sd)
{
    int chain = blockIdx.x * 256 + threadIdx.x;
    int d = chain & 511;
    float wdec = -__expf(sd[d] * (1.0f / (float)TT));
    float Lw = (float)CHLEN * wdec;

    float A = 0.f, B = 0.f, P = -1e38f;
    for (int j = 0; j < NCHUNK; j++) {
        g_pa[j * NCHAIN + chain] = A;
        g_pb[j * NCHAIN + chain] = B;
        g_pp[j * NCHAIN + chain] = P;
        float ca = g_sa[j * NCHAIN + chain];
        float cb = g_sb[j * NCHAIN + chain];
        float cp = g_sp[j * NCHAIN + chain];
        float np = P + Lw;
        float p  = fmaxf(np, cp);
        float e1 = __expf(np - p);
        float e2 = __expf(cp - p);
        A = e1 * A + e2 * ca;
        B = e1 * B + e2 * cb;
        P = p;
    }
}

__global__ __launch_bounds__(256) void wkv_pass3(const float* __restrict__ sd,
                                                 const float* __restrict__ sf)
{
    int g     = blockIdx.x * 256 + threadIdx.x;
    int chain = g & (NCHAIN - 1);
    int chunk = g >> 12;
    int b = chain >> 9;
    int d = chain & 511;
    int c = d & 255;
    bool second = d >= 256;

    float wdec = -__expf(sd[d] * (1.0f / (float)TT));
    float u    =  sf[d] * (1.0f / (float)TT);

    const size_t base = (size_t)b * TT * CC + c;
    __half* xsp = g_xsh + (size_t)b * TT * DD + d;

    float a  = g_pa[chunk * NCHAIN + chain];
    float bb = g_pb[chunk * NCHAIN + chain];
    float pp = g_pp[chunk * NCHAIN + chain];

    int tstart = chunk * CHLEN;
    for (int t0 = tstart; t0 < tstart + CHLEN; t0 += 8) {
        float kb[8], vb[8], sb[8];
        #pragma unroll
        for (int i = 0; i < 8; i++) {
            int t  = t0 + i;
            int ti = second ? (((t & 63) << 6) | (t >> 6)) : t;
            size_t off = base + (size_t)ti * CC;
            kb[i] = g_k[off];
            vb[i] = g_v[off];
            sb[i] = g_sr[base + (size_t)t * CC];
        }
        #pragma unroll
        for (int i = 0; i < 8; i++) {
            float kt = kb[i], vt = vb[i];
            float ww = u + kt;
            float d1 = pp - ww;
            float e  = __expf(-fabsf(d1));
            float e1 = (d1 >= 0.f) ? 1.f : e;
            float e2 = (d1 >= 0.f) ? e : 1.f;
            float out = __fdividef(e1 * a + e2 * vt, e1 * bb + e2);
            wkv_state(kt, vt, wdec, a, bb, pp);
            xsp[(size_t)(t0 + i) * DD] = __float2half_rn(out * sb[i]);
        }
    }
}

// ---------------- launch -----------------------------------------------------
extern "C" void kernel_launch(void* const* d_in, const int* in_sizes, int n_in,
                              void* d_out, int out_size)
{
    const float* x     = (const float*)d_in[0];
    const float* alpha = (const float*)d_in[1];
    const float* cw1   = (const float*)d_in[2];
    const float* cw3   = (const float*)d_in[3];
    const float* cw5   = (const float*)d_in[4];
    const float* Wk    = (const float*)d_in[5];
    const float* Wv    = (const float*)d_in[6];
    const float* Wr    = (const float*)d_in[7];
    const float* Wo    = (const float*)d_in[8];
    const float* sd    = (const float*)d_in[9];
    const float* sf    = (const float*)d_in[10];

    float *k, *v, *sr;
    __half *xfh, *xsh, *wkh, *wvh, *wrh, *woh;
    cudaGetSymbolAddress((void**)&xfh, g_xfh);
    cudaGetSymbolAddress((void**)&k,   g_k);
    cudaGetSymbolAddress((void**)&v,   g_v);
    cudaGetSymbolAddress((void**)&sr,  g_sr);
    cudaGetSymbolAddress((void**)&xsh, g_xsh);
    cudaGetSymbolAddress((void**)&wkh, g_wkh);
    cudaGetSymbolAddress((void**)&wvh, g_wvh);
    cudaGetSymbolAddress((void**)&wrh, g_wrh);
    cudaGetSymbolAddress((void**)&woh, g_woh);

    cudaFuncSetAttribute(gemm_qkv_kernel,
                         cudaFuncAttributeMaxDynamicSharedMemorySize, GS_BYTES);

    round_weights_kernel<<<(CC * DD + 255) / 256, 256>>>(Wk, Wv, Wr, Wo);
    combine_weights_kernel<<<1, 256>>>(alpha, cw1, cw3, cw5);
    omni_conv_kernel<<<BATCH * 32, 256>>>(x);

    // fused k / v / r(sigmoid) gemms: grid.x = 6 (3 groups x 2 n-blocks)
    dim3 g3(6, MM / 128);
    gemm_qkv_kernel<<<g3, 256, GS_BYTES>>>(xfh, wkh, wvh, wrh, k, v, sr, CC, 4);

    wkv_pass1<<<(NCHAIN * NCHUNK) / 256, 256>>>(sd);
    wkv_pass2<<<NCHAIN / 256, 256>>>(sd);
    wkv_pass3<<<(NCHAIN * NCHUNK) / 256, 256>>>(sd, sf);

    // output projection: grid.x = 2 (group 0 only), K = 512
    dim3 g1(2, MM / 128);
    gemm_qkv_kernel<<<g1, 256, GS_BYTES>>>(xsh, woh, woh, woh,
                                           (float*)d_out, (float*)d_out,
                                           (float*)d_out, DD, 0);
}